// round 5
// baseline (speedup 1.0000x reference)
#include <cuda_runtime.h>

#define NB 1024
#define PIX 784
#define ZDIM 848

__device__ float z_buf[NB * ZDIM];

// ---------------- packed f32x2 helpers ----------------
__device__ __forceinline__ void lds_v2u64(unsigned long long &a, unsigned long long &b,
                                          unsigned saddr) {
    asm volatile("ld.shared.v2.u64 {%0,%1},[%2];" : "=l"(a), "=l"(b) : "r"(saddr));
}
__device__ __forceinline__ unsigned long long pk2(float lo, float hi) {
    unsigned long long r;
    asm("mov.b64 %0,{%1,%2};" : "=l"(r) : "f"(lo), "f"(hi));
    return r;
}
__device__ __forceinline__ unsigned long long fmaf2(unsigned long long a,
                                                    unsigned long long b,
                                                    unsigned long long c) {
    unsigned long long r;
    asm("fma.rn.f32x2 %0,%1,%2,%3;" : "=l"(r) : "l"(a), "l"(b), "l"(c));
    return r;
}
__device__ __forceinline__ void upk2(float &lo, float &hi, unsigned long long v) {
    asm("mov.b64 {%0,%1},%2;" : "=f"(lo), "=f"(hi) : "l"(v));
}

// ---------------------------------------------------------------------------
// Kernel 1: TDA branches. Landscape top-k collapses to (max, min1, min2).
// ---------------------------------------------------------------------------
__global__ void __launch_bounds__(128) tda_kernel(
    const float* __restrict__ dtm1, const float* __restrict__ dtm2,
    const float* __restrict__ g1w, const float* __restrict__ g1b,
    const float* __restrict__ g2w, const float* __restrict__ g2b)
{
    int b = blockIdx.x;
    int tid = threadIdx.x;
    const float4* v1 = (const float4*)(dtm1 + b * PIX);
    const float4* v2 = (const float4*)(dtm2 + b * PIX);

    float mx1 = -1e30f, a1 = 1e30f, a2 = 1e30f;
    float mx2 = -1e30f, c1 = 1e30f, c2 = 1e30f;
    for (int i = tid; i < 196; i += 128) {
        float4 u4 = v1[i];
        float4 w4 = v2[i];
        #pragma unroll
        for (int j = 0; j < 4; j++) {
            float u = (j == 0) ? u4.x : (j == 1) ? u4.y : (j == 2) ? u4.z : u4.w;
            mx1 = fmaxf(mx1, u);
            if (u < a1) { a2 = a1; a1 = u; } else if (u < a2) a2 = u;
            float w = (j == 0) ? w4.x : (j == 1) ? w4.y : (j == 2) ? w4.z : w4.w;
            mx2 = fmaxf(mx2, w);
            if (w < c1) { c2 = c1; c1 = w; } else if (w < c2) c2 = w;
        }
    }
    #pragma unroll
    for (int off = 16; off; off >>= 1) {
        mx1 = fmaxf(mx1, __shfl_xor_sync(~0u, mx1, off));
        float o1 = __shfl_xor_sync(~0u, a1, off);
        float o2 = __shfl_xor_sync(~0u, a2, off);
        float n1 = fminf(a1, o1);
        float n2 = fminf(fmaxf(a1, o1), fminf(a2, o2));
        a1 = n1; a2 = n2;
        mx2 = fmaxf(mx2, __shfl_xor_sync(~0u, mx2, off));
        float p1 = __shfl_xor_sync(~0u, c1, off);
        float p2 = __shfl_xor_sync(~0u, c2, off);
        float q1 = fminf(c1, p1);
        float q2 = fminf(fmaxf(c1, p1), fminf(c2, p2));
        c1 = q1; c2 = q2;
    }
    __shared__ float red[4][6];
    __shared__ float fin[6];
    if ((tid & 31) == 0) {
        int w = tid >> 5;
        red[w][0] = mx1; red[w][1] = a1; red[w][2] = a2;
        red[w][3] = mx2; red[w][4] = c1; red[w][5] = c2;
    }
    __syncthreads();
    if (tid == 0) {
        float M1 = red[0][0], A1 = red[0][1], A2 = red[0][2];
        float M2 = red[0][3], C1 = red[0][4], C2 = red[0][5];
        #pragma unroll
        for (int w = 1; w < 4; w++) {
            M1 = fmaxf(M1, red[w][0]);
            float o1 = red[w][1], o2 = red[w][2];
            float n1 = fminf(A1, o1);
            float n2 = fminf(fmaxf(A1, o1), fminf(A2, o2));
            A1 = n1; A2 = n2;
            M2 = fmaxf(M2, red[w][3]);
            float p1 = red[w][4], p2 = red[w][5];
            float q1 = fminf(C1, p1);
            float q2 = fminf(fmaxf(C1, p1), fminf(C2, p2));
            C1 = q1; C2 = q2;
        }
        fin[0] = M1; fin[1] = A1; fin[2] = A2;
        fin[3] = M2; fin[4] = C1; fin[5] = C2;
    }
    __syncthreads();

    __shared__ float lam1[64], lam2[64];
    if (tid < 64) {
        int k = tid >> 5, t = tid & 31;
        float tv1 = 0.01f + (float)t * (0.28f / 31.0f);
        float tv2 = 0.05f + (float)t * (0.25f / 31.0f);
        float m1 = k ? fin[2] : fin[1];
        float m2 = k ? fin[5] : fin[4];
        lam1[tid] = fmaxf(0.0f, fminf(tv1 - m1, fin[0] - tv1));
        lam2[tid] = fmaxf(0.0f, fminf(tv2 - m2, fin[3] - tv2));
    }
    __syncthreads();

    if (tid < 32) {
        float acc = g1b[tid];
        #pragma unroll
        for (int i = 0; i < 64; i++) acc += lam1[i] * g1w[i * 32 + tid];
        z_buf[b * ZDIM + 784 + tid] = fmaxf(acc, 0.0f);
    } else if (tid < 64) {
        int j = tid - 32;
        float acc = g2b[j];
        #pragma unroll
        for (int i = 0; i < 64; i++) acc += lam2[i] * g2w[i * 32 + j];
        z_buf[b * ZDIM + 816 + j] = fmaxf(acc, 0.0f);
    }
}

// ---------------------------------------------------------------------------
// Kernel 2: fused conv1+ReLU+conv2+ReLU, quarter-split for 4 CTAs/SM.
//   CTA(b, y) computes output rows [7y, 7y+7). Needs h1 rows 7y-1..7y+7
//   (9 local rows; out-of-image rows zeroed so F is zero there) and x rows
//   7y-2..7y+8 (11 rows).
//   F[q,k] = sum_c h1[q,c] w2[k,c]; out[p] = relu(b2 + sum_k F[p+d_k,k]).
//   F is column-padded (stride 30, zero edges) -> branch-free gather.
// smem floats: xs[11*32]=352 | h1[252*36]=9072 | F[9*30*9]=2430  => 47416 B
// ---------------------------------------------------------------------------
#define XS_FL   (11 * 32)
#define H1_FL   (9 * 28 * 36)
#define F_FL    (9 * 30 * 9)
#define CSMEM_FLOATS (XS_FL + H1_FL + F_FL)

__global__ void __launch_bounds__(256, 4) conv_kernel(
    const float* __restrict__ x,
    const float* __restrict__ w1, const float* __restrict__ b1,
    const float* __restrict__ w2, const float* __restrict__ b2)
{
    extern __shared__ float smem[];
    float* xs = smem;             // 11 rows x 32 cols (col index = gc+1), zero halo
    float* h1 = smem + XS_FL;     // [local_pixel 0..251][c], stride 36
    float* Fb = h1 + H1_FL;       // [local_row 0..8][col 0..29][k], row-padded cols

    int b = blockIdx.x;
    int base = 7 * blockIdx.y;    // output row base (0,7,14,21)
    int tid = threadIdx.x;
    int lane = tid & 31, wid = tid >> 5;

    // ---- load x tile + zero F edge columns
    for (int i = tid; i < XS_FL; i += 256) {
        int r = i >> 5, c = i & 31;
        int gr = base - 2 + r, gc = c - 1;
        float v = 0.0f;
        if (gr >= 0 && gr < 28 && gc >= 0 && gc < 28)
            v = x[b * 784 + gr * 28 + gc];
        xs[i] = v;
    }
    if (tid < 162) {  // 9 rows x 2 edge cols x 9 taps
        int lr = tid / 18, rem = tid % 18;
        int colp = (rem < 9) ? 0 : 29;
        int k = rem % 9;
        Fb[(lr * 30 + colp) * 9 + k] = 0.0f;
    }
    __syncthreads();

    // ---- conv1: lane = channel, warp = local h1 row (warp 0 also row 8)
    {
        int c = lane;
        float wk[9];
        #pragma unroll
        for (int k = 0; k < 9; k++) wk[k] = w1[k * 32 + c];
        float bc = b1[c];

        for (int lr = wid; lr < 9; lr += 8) {
            int gr = base - 1 + lr;
            float* hrow = h1 + lr * 28 * 36 + c;
            if (gr < 0 || gr >= 28) {
                #pragma unroll 4
                for (int col = 0; col < 28; col++) hrow[col * 36] = 0.0f;
            } else {
                const float* xr = xs + lr * 32;     // rows lr, lr+1, lr+2
                float a0 = xr[0],   b0 = xr[1];
                float a1v = xr[32], b1v = xr[33];
                float a2v = xr[64], b2v = xr[65];
                #pragma unroll 4
                for (int col = 0; col < 28; col++) {
                    float c0  = xr[col + 2];
                    float c1v = xr[32 + col + 2];
                    float c2v = xr[64 + col + 2];
                    float acc = bc;
                    acc += a0  * wk[0]; acc += b0  * wk[1]; acc += c0  * wk[2];
                    acc += a1v * wk[3]; acc += b1v * wk[4]; acc += c1v * wk[5];
                    acc += a2v * wk[6]; acc += b2v * wk[7]; acc += c2v * wk[8];
                    hrow[col * 36] = fmaxf(acc, 0.0f);
                    a0 = b0;   b0 = c0;
                    a1v = b1v; b1v = c1v;
                    a2v = b2v; b2v = c2v;
                }
            }
        }
    }
    __syncthreads();

    // ---- F-pass: warp = tap k (warp 0 also k=8), lane = column (0..27)
    if (lane < 28) {
        for (int k = wid; k < 9; k += 8) {
            unsigned long long wp[16];          // packed channel-pair weights (warp-uniform)
            #pragma unroll
            for (int j = 0; j < 16; j++)
                wp[j] = pk2(w2[k * 32 + 2 * j], w2[k * 32 + 2 * j + 1]);
            #pragma unroll
            for (int lr = 0; lr < 9; lr++) {
                int lp = lr * 28 + lane;
                unsigned saddr = (unsigned)__cvta_generic_to_shared(h1 + lp * 36);
                unsigned long long s0 = 0, s1 = 0, s2 = 0, s3 = 0;
                #pragma unroll
                for (int j = 0; j < 4; j++) {
                    unsigned long long d0, d1, d2, d3;
                    lds_v2u64(d0, d1, saddr + j * 32);
                    lds_v2u64(d2, d3, saddr + j * 32 + 16);
                    s0 = fmaf2(d0, wp[4 * j + 0], s0);
                    s1 = fmaf2(d1, wp[4 * j + 1], s1);
                    s2 = fmaf2(d2, wp[4 * j + 2], s2);
                    s3 = fmaf2(d3, wp[4 * j + 3], s3);
                }
                float f0, f1, f2, f3, f4, f5, f6, f7;
                upk2(f0, f1, s0); upk2(f2, f3, s1);
                upk2(f4, f5, s2); upk2(f6, f7, s3);
                Fb[(lr * 30 + lane + 1) * 9 + k] =
                    ((f0 + f1) + (f2 + f3)) + ((f4 + f5) + (f6 + f7));
            }
        }
    }
    __syncthreads();

    // ---- gather: out[p] = relu(b2 + sum_k F[p+d_k, k]), fully branch-free
    if (tid < 196) {
        int r = tid / 28, oc = tid - r * 28;
        float acc = b2[0];
        #pragma unroll
        for (int dy = 0; dy < 3; dy++)
            #pragma unroll
            for (int dx = 0; dx < 3; dx++)
                acc += Fb[((r + dy) * 30 + oc + dx) * 9 + dy * 3 + dx];
        z_buf[b * ZDIM + (base + r) * 28 + oc] = fmaxf(acc, 0.0f);
    }
}

// ---------------------------------------------------------------------------
// Kernel 3: MLP head. 8 samples/block, 256 threads.
//   fc1: thread = (sample s = tid>>5, column-pair jq = tid&31) -> float2
//   weight loads (halved LDG count), two independent acc chains.
// ---------------------------------------------------------------------------
__global__ void __launch_bounds__(256) mlp_kernel(
    const float* __restrict__ fc1w, const float* __restrict__ fc1b,
    const float* __restrict__ fc2w, const float* __restrict__ fc2b,
    float* __restrict__ out)
{
    __shared__ float zt[8 * ZDIM];
    __shared__ float ys[8 * 65];
    int tid = threadIdx.x;
    int bbase = blockIdx.x * 8;

    const float4* src = (const float4*)(z_buf + bbase * ZDIM);
    float4* dst = (float4*)zt;
    for (int i = tid; i < 8 * ZDIM / 4; i += 256)
        dst[i] = src[i];
    __syncthreads();

    {
        int s = tid >> 5, jq = tid & 31;
        const float2* wv = (const float2*)fc1w;      // wv[i*32 + jq] = cols (2jq, 2jq+1)
        const float* zs = zt + s * ZDIM;
        float a0 = 0.0f, a1 = 0.0f;
        #pragma unroll 8
        for (int i = 0; i < ZDIM; i++) {
            float zv = zs[i];
            float2 w = wv[i * 32 + jq];
            a0 += zv * w.x;
            a1 += zv * w.y;
        }
        int j0 = 2 * jq;
        ys[s * 65 + j0]     = fmaxf(a0 + fc1b[j0], 0.0f);
        ys[s * 65 + j0 + 1] = fmaxf(a1 + fc1b[j0 + 1], 0.0f);
    }
    __syncthreads();

    if (tid < 80) {
        int s = tid / 10, k = tid - s * 10;
        float acc = fc2b[k];
        #pragma unroll
        for (int jj = 0; jj < 64; jj++)
            acc += ys[s * 65 + jj] * fc2w[jj * 10 + k];
        out[(bbase + s) * 10 + k] = acc;
    }
}

// ---------------------------------------------------------------------------
extern "C" void kernel_launch(void* const* d_in, const int* in_sizes, int n_in,
                              void* d_out, int out_size)
{
    const float* x    = (const float*)d_in[0];
    const float* dtm1 = (const float*)d_in[1];
    const float* dtm2 = (const float*)d_in[2];
    const float* w1   = (const float*)d_in[3];
    const float* b1   = (const float*)d_in[4];
    const float* w2   = (const float*)d_in[5];
    const float* b2   = (const float*)d_in[6];
    const float* g1w  = (const float*)d_in[7];
    const float* g1b  = (const float*)d_in[8];
    const float* g2w  = (const float*)d_in[9];
    const float* g2b  = (const float*)d_in[10];
    const float* fc1w = (const float*)d_in[11];
    const float* fc1b = (const float*)d_in[12];
    const float* fc2w = (const float*)d_in[13];
    const float* fc2b = (const float*)d_in[14];
    float* out = (float*)d_out;

    cudaFuncSetAttribute(conv_kernel, cudaFuncAttributeMaxDynamicSharedMemorySize,
                         CSMEM_FLOATS * (int)sizeof(float));
    cudaFuncSetAttribute(conv_kernel, cudaFuncAttributePreferredSharedMemoryCarveout,
                         100);

    conv_kernel<<<dim3(NB, 4), 256, CSMEM_FLOATS * sizeof(float)>>>(x, w1, b1, w2, b2);
    tda_kernel<<<NB, 128>>>(dtm1, dtm2, g1w, g1b, g2w, g2b);
    mlp_kernel<<<NB / 8, 256>>>(fc1w, fc1b, fc2w, fc2b, out);
}

// round 6
// speedup vs baseline: 1.4779x; 1.4779x over previous
#include <cuda_runtime.h>

#define NB 1024
#define PIX 784
#define ZDIM 848

__device__ float z_buf[NB * ZDIM];

// ---------------- packed f32x2 helpers ----------------
__device__ __forceinline__ void lds_v2u64(unsigned long long &a, unsigned long long &b,
                                          unsigned saddr) {
    asm volatile("ld.shared.v2.u64 {%0,%1},[%2];" : "=l"(a), "=l"(b) : "r"(saddr));
}
__device__ __forceinline__ unsigned long long addf2(unsigned long long a,
                                                    unsigned long long b) {
    unsigned long long r;
    asm("add.rn.f32x2 %0,%1,%2;" : "=l"(r) : "l"(a), "l"(b));
    return r;
}
__device__ __forceinline__ void upk2(float &lo, float &hi, unsigned long long v) {
    asm("mov.b64 {%0,%1},%2;" : "=f"(lo), "=f"(hi) : "l"(v));
}

// ---------------------------------------------------------------------------
// Fused kernel. Blocks [0,4096): conv quarter-tiles. Blocks [4096,5120): TDA.
//
// Conv per CTA (b, q): output rows [7q, 7q+7).
//   conv1 (lane=channel, warp=h1 row): h1 rows 7q-1..7q+7 (9 rows), column-
//     padded stride-30 (zero cols 0,29), per-pixel channel stride 36.
//   G-pass (lane=channel, warp=output row): per-channel 3x3 conv of h1 with
//     w2 -> G[p,c]; 3 sliding-window LDS per pixel, conflict-free.
//   sum-pass (thread=pixel): out[p] = relu(b2 + sum_c G[p,c]); 8 LDS.128 at
//     stride 144B = 4-phase floor.
// smem floats: xs[11*32]=352 | h1[9*30*36]=9720 | Gs[196*36]=7056 => 68512 B
// ---------------------------------------------------------------------------
#define XS_FL   (11 * 32)
#define H1_FL   (9 * 30 * 36)
#define G_FL    (196 * 36)
#define CSMEM_FLOATS (XS_FL + H1_FL + G_FL)

__global__ void __launch_bounds__(288, 3) fused_kernel(
    const float* __restrict__ x,
    const float* __restrict__ w1, const float* __restrict__ b1,
    const float* __restrict__ w2, const float* __restrict__ b2,
    const float* __restrict__ dtm1, const float* __restrict__ dtm2,
    const float* __restrict__ g1w, const float* __restrict__ g1b,
    const float* __restrict__ g2w, const float* __restrict__ g2b)
{
    extern __shared__ float smem[];
    int tid = threadIdx.x;
    int lane = tid & 31, wid = tid >> 5;

    if (blockIdx.x < 4096) {
        // =================== CONV PATH ===================
        float* xs = smem;                 // 11 rows x 32 (col idx = gc+1)
        float* h1 = smem + XS_FL;         // [lr 0..8][cp 0..29][c], stride 36
        float* Gs = h1 + H1_FL;           // [p 0..195][c], stride 36

        int b = blockIdx.x >> 2;
        int base = 7 * (blockIdx.x & 3);  // output row base: 0,7,14,21

        // ---- load x tile (rows base-2..base+8, zero halo) + zero h1 pad cols
        for (int i = tid; i < XS_FL; i += 288) {
            int r = i >> 5, c = i & 31;
            int gr = base - 2 + r, gc = c - 1;
            float v = 0.0f;
            if (gr >= 0 && gr < 28 && gc >= 0 && gc < 28)
                v = x[b * 784 + gr * 28 + gc];
            xs[i] = v;
        }
        for (int i = tid; i < 9 * 2 * 32; i += 288) {
            int lr = i >> 6;
            int cp = ((i >> 5) & 1) ? 29 : 0;
            int c = i & 31;
            h1[(lr * 30 + cp) * 36 + c] = 0.0f;
        }
        __syncthreads();

        // ---- conv1: lane = channel, warp = h1 local row (9 warps, 9 rows)
        {
            int c = lane;
            float wk[9];
            #pragma unroll
            for (int k = 0; k < 9; k++) wk[k] = w1[k * 32 + c];
            float bc = b1[c];

            int lr = wid;                        // 0..8
            int gr = base - 1 + lr;
            float* hrow = h1 + (lr * 30 + 1) * 36 + c;
            if (gr < 0 || gr >= 28) {
                #pragma unroll 4
                for (int col = 0; col < 28; col++) hrow[col * 36] = 0.0f;
            } else {
                const float* xr = xs + lr * 32;  // x rows lr, lr+1, lr+2
                float a0 = xr[0],   b0 = xr[1];
                float a1v = xr[32], b1v = xr[33];
                float a2v = xr[64], b2v = xr[65];
                #pragma unroll 4
                for (int col = 0; col < 28; col++) {
                    float c0  = xr[col + 2];
                    float c1v = xr[32 + col + 2];
                    float c2v = xr[64 + col + 2];
                    float acc = bc;
                    acc += a0  * wk[0]; acc += b0  * wk[1]; acc += c0  * wk[2];
                    acc += a1v * wk[3]; acc += b1v * wk[4]; acc += c1v * wk[5];
                    acc += a2v * wk[6]; acc += b2v * wk[7]; acc += c2v * wk[8];
                    hrow[col * 36] = fmaxf(acc, 0.0f);
                    a0 = b0;   b0 = c0;
                    a1v = b1v; b1v = c1v;
                    a2v = b2v; b2v = c2v;
                }
            }
        }
        __syncthreads();

        // ---- G-pass: lane = channel, warp = output row r (warps 0..6)
        if (wid < 7) {
            int c = lane, r = wid;
            float wk[9];
            #pragma unroll
            for (int k = 0; k < 9; k++) wk[k] = w2[k * 32 + c];
            const float* h0 = h1 + ((r    ) * 30) * 36 + c;
            const float* hm = h1 + ((r + 1) * 30) * 36 + c;
            const float* h2 = h1 + ((r + 2) * 30) * 36 + c;
            float a0 = h0[0],  b0 = h0[36];
            float a1 = hm[0],  b1v = hm[36];
            float a2 = h2[0],  b2v = h2[36];
            float* grow = Gs + r * 28 * 36 + c;
            #pragma unroll 4
            for (int col = 0; col < 28; col++) {
                float c0 = h0[(col + 2) * 36];
                float c1 = hm[(col + 2) * 36];
                float c2 = h2[(col + 2) * 36];
                float acc;
                acc  = a0  * wk[0]; acc += b0  * wk[1]; acc += c0 * wk[2];
                acc += a1  * wk[3]; acc += b1v * wk[4]; acc += c1 * wk[5];
                acc += a2  * wk[6]; acc += b2v * wk[7]; acc += c2 * wk[8];
                grow[col * 36] = acc;
                a0 = b0;   b0 = c0;
                a1 = b1v;  b1v = c1;
                a2 = b2v;  b2v = c2;
            }
        }
        __syncthreads();

        // ---- sum-pass: thread = pixel p (0..195)
        if (tid < 196) {
            unsigned saddr = (unsigned)__cvta_generic_to_shared(Gs + tid * 36);
            unsigned long long s0, s1, s2, s3, s4, s5, s6, s7;
            {
                unsigned long long d0, d1, d2, d3;
                lds_v2u64(d0, d1, saddr);
                lds_v2u64(d2, d3, saddr + 16);
                s0 = d0; s1 = d1; s2 = d2; s3 = d3;
                lds_v2u64(d0, d1, saddr + 32);
                lds_v2u64(d2, d3, saddr + 48);
                s4 = d0; s5 = d1; s6 = d2; s7 = d3;
                lds_v2u64(d0, d1, saddr + 64);
                lds_v2u64(d2, d3, saddr + 80);
                s0 = addf2(s0, d0); s1 = addf2(s1, d1);
                s2 = addf2(s2, d2); s3 = addf2(s3, d3);
                lds_v2u64(d0, d1, saddr + 96);
                lds_v2u64(d2, d3, saddr + 112);
                s4 = addf2(s4, d0); s5 = addf2(s5, d1);
                s6 = addf2(s6, d2); s7 = addf2(s7, d3);
            }
            s0 = addf2(s0, s4); s1 = addf2(s1, s5);
            s2 = addf2(s2, s6); s3 = addf2(s3, s7);
            s0 = addf2(s0, s2); s1 = addf2(s1, s3);
            s0 = addf2(s0, s1);
            float lo, hi;
            upk2(lo, hi, s0);
            float acc = lo + hi + b2[0];
            z_buf[b * ZDIM + base * 28 + tid] = fmaxf(acc, 0.0f);
        }
        return;
    }

    // =================== TDA PATH ===================
    {
        int b = blockIdx.x - 4096;
        float* red  = smem;            // 9 warps x 6
        float* fin  = smem + 64;       // 6
        float* lam1 = smem + 80;       // 64
        float* lam2 = smem + 144;      // 64

        const float4* v1 = (const float4*)(dtm1 + b * PIX);
        const float4* v2 = (const float4*)(dtm2 + b * PIX);

        float mx1 = -1e30f, a1 = 1e30f, a2 = 1e30f;
        float mx2 = -1e30f, c1 = 1e30f, c2 = 1e30f;
        if (tid < 196) {
            float4 u4 = v1[tid];
            float4 w4 = v2[tid];
            #pragma unroll
            for (int j = 0; j < 4; j++) {
                float u = (j == 0) ? u4.x : (j == 1) ? u4.y : (j == 2) ? u4.z : u4.w;
                mx1 = fmaxf(mx1, u);
                if (u < a1) { a2 = a1; a1 = u; } else if (u < a2) a2 = u;
                float w = (j == 0) ? w4.x : (j == 1) ? w4.y : (j == 2) ? w4.z : w4.w;
                mx2 = fmaxf(mx2, w);
                if (w < c1) { c2 = c1; c1 = w; } else if (w < c2) c2 = w;
            }
        }
        #pragma unroll
        for (int off = 16; off; off >>= 1) {
            mx1 = fmaxf(mx1, __shfl_xor_sync(~0u, mx1, off));
            float o1 = __shfl_xor_sync(~0u, a1, off);
            float o2 = __shfl_xor_sync(~0u, a2, off);
            float n1 = fminf(a1, o1);
            float n2 = fminf(fmaxf(a1, o1), fminf(a2, o2));
            a1 = n1; a2 = n2;
            mx2 = fmaxf(mx2, __shfl_xor_sync(~0u, mx2, off));
            float p1 = __shfl_xor_sync(~0u, c1, off);
            float p2 = __shfl_xor_sync(~0u, c2, off);
            float q1 = fminf(c1, p1);
            float q2 = fminf(fmaxf(c1, p1), fminf(c2, p2));
            c1 = q1; c2 = q2;
        }
        if (lane == 0) {
            red[wid * 6 + 0] = mx1; red[wid * 6 + 1] = a1; red[wid * 6 + 2] = a2;
            red[wid * 6 + 3] = mx2; red[wid * 6 + 4] = c1; red[wid * 6 + 5] = c2;
        }
        __syncthreads();
        if (tid == 0) {
            float M1 = red[0], A1 = red[1], A2 = red[2];
            float M2 = red[3], C1 = red[4], C2 = red[5];
            #pragma unroll
            for (int w = 1; w < 9; w++) {
                M1 = fmaxf(M1, red[w * 6 + 0]);
                float o1 = red[w * 6 + 1], o2 = red[w * 6 + 2];
                float n1 = fminf(A1, o1);
                float n2 = fminf(fmaxf(A1, o1), fminf(A2, o2));
                A1 = n1; A2 = n2;
                M2 = fmaxf(M2, red[w * 6 + 3]);
                float p1 = red[w * 6 + 4], p2 = red[w * 6 + 5];
                float q1 = fminf(C1, p1);
                float q2 = fminf(fmaxf(C1, p1), fminf(C2, p2));
                C1 = q1; C2 = q2;
            }
            fin[0] = M1; fin[1] = A1; fin[2] = A2;
            fin[3] = M2; fin[4] = C1; fin[5] = C2;
        }
        __syncthreads();

        if (tid < 128) {
            int k = (tid >> 5) & 1, t = tid & 31;
            if (tid < 64) {
                float tv1 = 0.01f + (float)t * (0.28f / 31.0f);
                float m1 = k ? fin[2] : fin[1];
                lam1[tid] = fmaxf(0.0f, fminf(tv1 - m1, fin[0] - tv1));
            } else {
                float tv2 = 0.05f + (float)t * (0.25f / 31.0f);
                float m2 = k ? fin[5] : fin[4];
                lam2[tid - 64] = fmaxf(0.0f, fminf(tv2 - m2, fin[3] - tv2));
            }
        }
        __syncthreads();

        if (tid < 32) {
            float acc = g1b[tid];
            #pragma unroll
            for (int i = 0; i < 64; i++) acc += lam1[i] * g1w[i * 32 + tid];
            z_buf[b * ZDIM + 784 + tid] = fmaxf(acc, 0.0f);
        } else if (tid < 64) {
            int j = tid - 32;
            float acc = g2b[j];
            #pragma unroll
            for (int i = 0; i < 64; i++) acc += lam2[i] * g2w[i * 32 + j];
            z_buf[b * ZDIM + 816 + j] = fmaxf(acc, 0.0f);
        }
    }
}

// ---------------------------------------------------------------------------
// MLP head: 4 samples/block, 256 threads, grid 256 (full SM coverage).
//   fc1: thread = (sample s = tid>>6, column j = tid&63); z via float4 LDS.
// ---------------------------------------------------------------------------
__global__ void __launch_bounds__(256) mlp_kernel(
    const float* __restrict__ fc1w, const float* __restrict__ fc1b,
    const float* __restrict__ fc2w, const float* __restrict__ fc2b,
    float* __restrict__ out)
{
    __shared__ float zt[4 * ZDIM];
    __shared__ float ys[4 * 68];
    int tid = threadIdx.x;
    int bbase = blockIdx.x * 4;

    const float4* src = (const float4*)(z_buf + bbase * ZDIM);
    float4* dst = (float4*)zt;
    for (int i = tid; i < 4 * ZDIM / 4; i += 256)
        dst[i] = src[i];
    __syncthreads();

    {
        int s = tid >> 6, j = tid & 63;
        const float4* z4 = (const float4*)(zt + s * ZDIM);
        float acc0 = 0.0f, acc1 = 0.0f;
        #pragma unroll 4
        for (int i = 0; i < ZDIM / 4; i++) {
            float4 zv = z4[i];
            const float* wb = fc1w + i * 4 * 64 + j;
            acc0 += zv.x * wb[0];
            acc1 += zv.y * wb[64];
            acc0 += zv.z * wb[128];
            acc1 += zv.w * wb[192];
        }
        ys[s * 68 + j] = fmaxf(acc0 + acc1 + fc1b[j], 0.0f);
    }
    __syncthreads();

    if (tid < 40) {
        int s = tid / 10, k = tid - s * 10;
        float acc = fc2b[k];
        #pragma unroll
        for (int jj = 0; jj < 64; jj++)
            acc += ys[s * 68 + jj] * fc2w[jj * 10 + k];
        out[(bbase + s) * 10 + k] = acc;
    }
}

// ---------------------------------------------------------------------------
extern "C" void kernel_launch(void* const* d_in, const int* in_sizes, int n_in,
                              void* d_out, int out_size)
{
    const float* x    = (const float*)d_in[0];
    const float* dtm1 = (const float*)d_in[1];
    const float* dtm2 = (const float*)d_in[2];
    const float* w1   = (const float*)d_in[3];
    const float* b1   = (const float*)d_in[4];
    const float* w2   = (const float*)d_in[5];
    const float* b2   = (const float*)d_in[6];
    const float* g1w  = (const float*)d_in[7];
    const float* g1b  = (const float*)d_in[8];
    const float* g2w  = (const float*)d_in[9];
    const float* g2b  = (const float*)d_in[10];
    const float* fc1w = (const float*)d_in[11];
    const float* fc1b = (const float*)d_in[12];
    const float* fc2w = (const float*)d_in[13];
    const float* fc2b = (const float*)d_in[14];
    float* out = (float*)d_out;

    cudaFuncSetAttribute(fused_kernel, cudaFuncAttributeMaxDynamicSharedMemorySize,
                         CSMEM_FLOATS * (int)sizeof(float));
    cudaFuncSetAttribute(fused_kernel, cudaFuncAttributePreferredSharedMemoryCarveout,
                         100);

    fused_kernel<<<4096 + NB, 288, CSMEM_FLOATS * sizeof(float)>>>(
        x, w1, b1, w2, b2, dtm1, dtm2, g1w, g1b, g2w, g2b);
    mlp_kernel<<<NB / 4, 256>>>(fc1w, fc1b, fc2w, fc2b, out);
}

// round 9
// speedup vs baseline: 1.6456x; 1.1135x over previous
#include <cuda_runtime.h>

#define NB 1024
#define PIX 784
#define ZDIM 848

__device__ float z_buf[NB * ZDIM];

// ---------------- packed f32x2 helpers ----------------
__device__ __forceinline__ void lds_v2u64(unsigned long long &a, unsigned long long &b,
                                          unsigned saddr) {
    asm volatile("ld.shared.v2.u64 {%0,%1},[%2];" : "=l"(a), "=l"(b) : "r"(saddr));
}
__device__ __forceinline__ unsigned long long addf2(unsigned long long a,
                                                    unsigned long long b) {
    unsigned long long r;
    asm("add.rn.f32x2 %0,%1,%2;" : "=l"(r) : "l"(a), "l"(b));
    return r;
}
__device__ __forceinline__ void upk2(float &lo, float &hi, unsigned long long v) {
    asm("mov.b64 {%0,%1},%2;" : "=f"(lo), "=f"(hi) : "l"(v));
}

// ---------------------------------------------------------------------------
// Fused kernel. Blocks [0,4096): conv quarter-tiles. Blocks [4096,5120): TDA.
// (unchanged from round 6 — 65.6us -> ~21us win, protected)
// ---------------------------------------------------------------------------
#define XS_FL   (11 * 32)
#define H1_FL   (9 * 30 * 36)
#define G_FL    (196 * 36)
#define CSMEM_FLOATS (XS_FL + H1_FL + G_FL)

__global__ void __launch_bounds__(288, 3) fused_kernel(
    const float* __restrict__ x,
    const float* __restrict__ w1, const float* __restrict__ b1,
    const float* __restrict__ w2, const float* __restrict__ b2,
    const float* __restrict__ dtm1, const float* __restrict__ dtm2,
    const float* __restrict__ g1w, const float* __restrict__ g1b,
    const float* __restrict__ g2w, const float* __restrict__ g2b)
{
    extern __shared__ float smem[];
    int tid = threadIdx.x;
    int lane = tid & 31, wid = tid >> 5;

    if (blockIdx.x < 4096) {
        // =================== CONV PATH ===================
        float* xs = smem;                 // 11 rows x 32 (col idx = gc+1)
        float* h1 = smem + XS_FL;         // [lr 0..8][cp 0..29][c], stride 36
        float* Gs = h1 + H1_FL;           // [p 0..195][c], stride 36

        int b = blockIdx.x >> 2;
        int base = 7 * (blockIdx.x & 3);  // output row base: 0,7,14,21

        for (int i = tid; i < XS_FL; i += 288) {
            int r = i >> 5, c = i & 31;
            int gr = base - 2 + r, gc = c - 1;
            float v = 0.0f;
            if (gr >= 0 && gr < 28 && gc >= 0 && gc < 28)
                v = x[b * 784 + gr * 28 + gc];
            xs[i] = v;
        }
        for (int i = tid; i < 9 * 2 * 32; i += 288) {
            int lr = i >> 6;
            int cp = ((i >> 5) & 1) ? 29 : 0;
            int c = i & 31;
            h1[(lr * 30 + cp) * 36 + c] = 0.0f;
        }
        __syncthreads();

        // ---- conv1: lane = channel, warp = h1 local row (9 warps, 9 rows)
        {
            int c = lane;
            float wk[9];
            #pragma unroll
            for (int k = 0; k < 9; k++) wk[k] = w1[k * 32 + c];
            float bc = b1[c];

            int lr = wid;                        // 0..8
            int gr = base - 1 + lr;
            float* hrow = h1 + (lr * 30 + 1) * 36 + c;
            if (gr < 0 || gr >= 28) {
                #pragma unroll 4
                for (int col = 0; col < 28; col++) hrow[col * 36] = 0.0f;
            } else {
                const float* xr = xs + lr * 32;  // x rows lr, lr+1, lr+2
                float a0 = xr[0],   b0 = xr[1];
                float a1v = xr[32], b1v = xr[33];
                float a2v = xr[64], b2v = xr[65];
                #pragma unroll 4
                for (int col = 0; col < 28; col++) {
                    float c0  = xr[col + 2];
                    float c1v = xr[32 + col + 2];
                    float c2v = xr[64 + col + 2];
                    float acc = bc;
                    acc += a0  * wk[0]; acc += b0  * wk[1]; acc += c0  * wk[2];
                    acc += a1v * wk[3]; acc += b1v * wk[4]; acc += c1v * wk[5];
                    acc += a2v * wk[6]; acc += b2v * wk[7]; acc += c2v * wk[8];
                    hrow[col * 36] = fmaxf(acc, 0.0f);
                    a0 = b0;   b0 = c0;
                    a1v = b1v; b1v = c1v;
                    a2v = b2v; b2v = c2v;
                }
            }
        }
        __syncthreads();

        // ---- G-pass: lane = channel, warp = output row r (warps 0..6)
        if (wid < 7) {
            int c = lane, r = wid;
            float wk[9];
            #pragma unroll
            for (int k = 0; k < 9; k++) wk[k] = w2[k * 32 + c];
            const float* h0 = h1 + ((r    ) * 30) * 36 + c;
            const float* hm = h1 + ((r + 1) * 30) * 36 + c;
            const float* h2 = h1 + ((r + 2) * 30) * 36 + c;
            float a0 = h0[0],  b0 = h0[36];
            float a1 = hm[0],  b1v = hm[36];
            float a2 = h2[0],  b2v = h2[36];
            float* grow = Gs + r * 28 * 36 + c;
            #pragma unroll 4
            for (int col = 0; col < 28; col++) {
                float c0 = h0[(col + 2) * 36];
                float c1 = hm[(col + 2) * 36];
                float c2 = h2[(col + 2) * 36];
                float acc;
                acc  = a0  * wk[0]; acc += b0  * wk[1]; acc += c0 * wk[2];
                acc += a1  * wk[3]; acc += b1v * wk[4]; acc += c1 * wk[5];
                acc += a2  * wk[6]; acc += b2v * wk[7]; acc += c2 * wk[8];
                grow[col * 36] = acc;
                a0 = b0;   b0 = c0;
                a1 = b1v;  b1v = c1;
                a2 = b2v;  b2v = c2;
            }
        }
        __syncthreads();

        // ---- sum-pass: thread = pixel p (0..195)
        if (tid < 196) {
            unsigned saddr = (unsigned)__cvta_generic_to_shared(Gs + tid * 36);
            unsigned long long s0, s1, s2, s3, s4, s5, s6, s7;
            {
                unsigned long long d0, d1, d2, d3;
                lds_v2u64(d0, d1, saddr);
                lds_v2u64(d2, d3, saddr + 16);
                s0 = d0; s1 = d1; s2 = d2; s3 = d3;
                lds_v2u64(d0, d1, saddr + 32);
                lds_v2u64(d2, d3, saddr + 48);
                s4 = d0; s5 = d1; s6 = d2; s7 = d3;
                lds_v2u64(d0, d1, saddr + 64);
                lds_v2u64(d2, d3, saddr + 80);
                s0 = addf2(s0, d0); s1 = addf2(s1, d1);
                s2 = addf2(s2, d2); s3 = addf2(s3, d3);
                lds_v2u64(d0, d1, saddr + 96);
                lds_v2u64(d2, d3, saddr + 112);
                s4 = addf2(s4, d0); s5 = addf2(s5, d1);
                s6 = addf2(s6, d2); s7 = addf2(s7, d3);
            }
            s0 = addf2(s0, s4); s1 = addf2(s1, s5);
            s2 = addf2(s2, s6); s3 = addf2(s3, s7);
            s0 = addf2(s0, s2); s1 = addf2(s1, s3);
            s0 = addf2(s0, s1);
            float lo, hi;
            upk2(lo, hi, s0);
            float acc = lo + hi + b2[0];
            z_buf[b * ZDIM + base * 28 + tid] = fmaxf(acc, 0.0f);
        }
        return;
    }

    // =================== TDA PATH ===================
    {
        int b = blockIdx.x - 4096;
        float* red  = smem;            // 9 warps x 6
        float* fin  = smem + 64;       // 6
        float* lam1 = smem + 80;       // 64
        float* lam2 = smem + 144;      // 64

        const float4* v1 = (const float4*)(dtm1 + b * PIX);
        const float4* v2 = (const float4*)(dtm2 + b * PIX);

        float mx1 = -1e30f, a1 = 1e30f, a2 = 1e30f;
        float mx2 = -1e30f, c1 = 1e30f, c2 = 1e30f;
        if (tid < 196) {
            float4 u4 = v1[tid];
            float4 w4 = v2[tid];
            #pragma unroll
            for (int j = 0; j < 4; j++) {
                float u = (j == 0) ? u4.x : (j == 1) ? u4.y : (j == 2) ? u4.z : u4.w;
                mx1 = fmaxf(mx1, u);
                if (u < a1) { a2 = a1; a1 = u; } else if (u < a2) a2 = u;
                float w = (j == 0) ? w4.x : (j == 1) ? w4.y : (j == 2) ? w4.z : w4.w;
                mx2 = fmaxf(mx2, w);
                if (w < c1) { c2 = c1; c1 = w; } else if (w < c2) c2 = w;
            }
        }
        #pragma unroll
        for (int off = 16; off; off >>= 1) {
            mx1 = fmaxf(mx1, __shfl_xor_sync(~0u, mx1, off));
            float o1 = __shfl_xor_sync(~0u, a1, off);
            float o2 = __shfl_xor_sync(~0u, a2, off);
            float n1 = fminf(a1, o1);
            float n2 = fminf(fmaxf(a1, o1), fminf(a2, o2));
            a1 = n1; a2 = n2;
            mx2 = fmaxf(mx2, __shfl_xor_sync(~0u, mx2, off));
            float p1 = __shfl_xor_sync(~0u, c1, off);
            float p2 = __shfl_xor_sync(~0u, c2, off);
            float q1 = fminf(c1, p1);
            float q2 = fminf(fmaxf(c1, p1), fminf(c2, p2));
            c1 = q1; c2 = q2;
        }
        if (lane == 0) {
            red[wid * 6 + 0] = mx1; red[wid * 6 + 1] = a1; red[wid * 6 + 2] = a2;
            red[wid * 6 + 3] = mx2; red[wid * 6 + 4] = c1; red[wid * 6 + 5] = c2;
        }
        __syncthreads();
        if (tid == 0) {
            float M1 = red[0], A1 = red[1], A2 = red[2];
            float M2 = red[3], C1 = red[4], C2 = red[5];
            #pragma unroll
            for (int w = 1; w < 9; w++) {
                M1 = fmaxf(M1, red[w * 6 + 0]);
                float o1 = red[w * 6 + 1], o2 = red[w * 6 + 2];
                float n1 = fminf(A1, o1);
                float n2 = fminf(fmaxf(A1, o1), fminf(A2, o2));
                A1 = n1; A2 = n2;
                M2 = fmaxf(M2, red[w * 6 + 3]);
                float p1 = red[w * 6 + 4], p2 = red[w * 6 + 5];
                float q1 = fminf(C1, p1);
                float q2 = fminf(fmaxf(C1, p1), fminf(C2, p2));
                C1 = q1; C2 = q2;
            }
            fin[0] = M1; fin[1] = A1; fin[2] = A2;
            fin[3] = M2; fin[4] = C1; fin[5] = C2;
        }
        __syncthreads();

        if (tid < 128) {
            int k = (tid >> 5) & 1, t = tid & 31;
            if (tid < 64) {
                float tv1 = 0.01f + (float)t * (0.28f / 31.0f);
                float m1 = k ? fin[2] : fin[1];
                lam1[tid] = fmaxf(0.0f, fminf(tv1 - m1, fin[0] - tv1));
            } else {
                float tv2 = 0.05f + (float)t * (0.25f / 31.0f);
                float m2 = k ? fin[5] : fin[4];
                lam2[tid - 64] = fmaxf(0.0f, fminf(tv2 - m2, fin[3] - tv2));
            }
        }
        __syncthreads();

        if (tid < 32) {
            float acc = g1b[tid];
            #pragma unroll
            for (int i = 0; i < 64; i++) acc += lam1[i] * g1w[i * 32 + tid];
            z_buf[b * ZDIM + 784 + tid] = fmaxf(acc, 0.0f);
        } else if (tid < 64) {
            int j = tid - 32;
            float acc = g2b[j];
            #pragma unroll
            for (int i = 0; i < 64; i++) acc += lam2[i] * g2w[i * 32 + j];
            z_buf[b * ZDIM + 816 + j] = fmaxf(acc, 0.0f);
        }
    }
}

// ---------------------------------------------------------------------------
// MLP head: 4 samples/block, 256 threads, grid 256.
//   fc1: thread = (sample s = tid>>6, column j = tid&63).
//   Software-pipelined fc1w prefetch: ring of 8 groups x 4 floats (32 regs in
//   flight -> MLP_eff ~32), z via broadcast LDS.128, 4 acc chains.
// ---------------------------------------------------------------------------
__global__ void __launch_bounds__(256, 2) mlp_kernel(
    const float* __restrict__ fc1w, const float* __restrict__ fc1b,
    const float* __restrict__ fc2w, const float* __restrict__ fc2b,
    float* __restrict__ out)
{
    __shared__ float zt[4 * ZDIM];
    __shared__ float ys[4 * 68];
    int tid = threadIdx.x;
    int bbase = blockIdx.x * 4;

    const float4* src = (const float4*)(z_buf + bbase * ZDIM);
    float4* dst = (float4*)zt;
    for (int i = tid; i < 4 * ZDIM / 4; i += 256)
        dst[i] = src[i];
    __syncthreads();

    {
        int s = tid >> 6, j = tid & 63;
        const float4* z4 = (const float4*)(zt + s * ZDIM);
        const float* wp = fc1w + j;

        // prefetch ring: 8 groups of 4 rows (rows = i4*4 + p)
        float wb[8][4];
        #pragma unroll
        for (int g = 0; g < 8; g++)
            #pragma unroll
            for (int p = 0; p < 4; p++)
                wb[g][p] = wp[(g * 4 + p) * 64];

        float a0 = 0.0f, a1 = 0.0f, a2 = 0.0f, a3 = 0.0f;
        // 212 float4-groups total: 26 iters x 8 groups = 208, tail 4
        #pragma unroll 1
        for (int it = 0; it < 26; it++) {
            int i4 = it * 8;
            #pragma unroll
            for (int g = 0; g < 8; g++) {
                float4 zv = z4[i4 + g];
                float w0 = wb[g][0], w1 = wb[g][1], w2 = wb[g][2], w3 = wb[g][3];
                int nxt = i4 + g + 8;
                int rb = (nxt < 212) ? nxt * 4 : 0;     // clamp: dummy reload
                #pragma unroll
                for (int p = 0; p < 4; p++)
                    wb[g][p] = wp[(rb + p) * 64];
                a0 += zv.x * w0;
                a1 += zv.y * w1;
                a2 += zv.z * w2;
                a3 += zv.w * w3;
            }
        }
        #pragma unroll
        for (int g = 0; g < 4; g++) {                    // groups 208..211
            float4 zv = z4[208 + g];
            a0 += zv.x * wb[g][0];
            a1 += zv.y * wb[g][1];
            a2 += zv.z * wb[g][2];
            a3 += zv.w * wb[g][3];
        }
        ys[s * 68 + j] = fmaxf((a0 + a1) + (a2 + a3) + fc1b[j], 0.0f);
    }
    __syncthreads();

    if (tid < 40) {
        int s = tid / 10, k = tid - s * 10;
        float acc = fc2b[k];
        #pragma unroll
        for (int jj = 0; jj < 64; jj++)
            acc += ys[s * 68 + jj] * fc2w[jj * 10 + k];
        out[(bbase + s) * 10 + k] = acc;
    }
}

// ---------------------------------------------------------------------------
extern "C" void kernel_launch(void* const* d_in, const int* in_sizes, int n_in,
                              void* d_out, int out_size)
{
    const float* x    = (const float*)d_in[0];
    const float* dtm1 = (const float*)d_in[1];
    const float* dtm2 = (const float*)d_in[2];
    const float* w1   = (const float*)d_in[3];
    const float* b1   = (const float*)d_in[4];
    const float* w2   = (const float*)d_in[5];
    const float* b2   = (const float*)d_in[6];
    const float* g1w  = (const float*)d_in[7];
    const float* g1b  = (const float*)d_in[8];
    const float* g2w  = (const float*)d_in[9];
    const float* g2b  = (const float*)d_in[10];
    const float* fc1w = (const float*)d_in[11];
    const float* fc1b = (const float*)d_in[12];
    const float* fc2w = (const float*)d_in[13];
    const float* fc2b = (const float*)d_in[14];
    float* out = (float*)d_out;

    cudaFuncSetAttribute(fused_kernel, cudaFuncAttributeMaxDynamicSharedMemorySize,
                         CSMEM_FLOATS * (int)sizeof(float));
    cudaFuncSetAttribute(fused_kernel, cudaFuncAttributePreferredSharedMemoryCarveout,
                         100);

    fused_kernel<<<4096 + NB, 288, CSMEM_FLOATS * sizeof(float)>>>(
        x, w1, b1, w2, b2, dtm1, dtm2, g1w, g1b, g2w, g2b);
    mlp_kernel<<<NB / 4, 256>>>(fc1w, fc1b, fc2w, fc2b, out);
}

// round 10
// speedup vs baseline: 1.8137x; 1.1022x over previous
#include <cuda_runtime.h>

#define NB 1024
#define PIX 784
#define ZDIM 848

__device__ float z_buf[NB * ZDIM];

// ---------------- packed f32x2 helpers ----------------
__device__ __forceinline__ void lds_v2u64(unsigned long long &a, unsigned long long &b,
                                          unsigned saddr) {
    asm volatile("ld.shared.v2.u64 {%0,%1},[%2];" : "=l"(a), "=l"(b) : "r"(saddr));
}
__device__ __forceinline__ unsigned long long addf2(unsigned long long a,
                                                    unsigned long long b) {
    unsigned long long r;
    asm("add.rn.f32x2 %0,%1,%2;" : "=l"(r) : "l"(a), "l"(b));
    return r;
}
__device__ __forceinline__ void upk2(float &lo, float &hi, unsigned long long v) {
    asm("mov.b64 {%0,%1},%2;" : "=f"(lo), "=f"(hi) : "l"(v));
}

// ---------------------------------------------------------------------------
// Fused kernel. Blocks [0,4096): conv quarter-tiles. Blocks [4096,5120): TDA.
// (unchanged — protected win)
// ---------------------------------------------------------------------------
#define XS_FL   (11 * 32)
#define H1_FL   (9 * 30 * 36)
#define G_FL    (196 * 36)
#define CSMEM_FLOATS (XS_FL + H1_FL + G_FL)

__global__ void __launch_bounds__(288, 3) fused_kernel(
    const float* __restrict__ x,
    const float* __restrict__ w1, const float* __restrict__ b1,
    const float* __restrict__ w2, const float* __restrict__ b2,
    const float* __restrict__ dtm1, const float* __restrict__ dtm2,
    const float* __restrict__ g1w, const float* __restrict__ g1b,
    const float* __restrict__ g2w, const float* __restrict__ g2b)
{
    extern __shared__ float smem[];
    int tid = threadIdx.x;
    int lane = tid & 31, wid = tid >> 5;

    if (blockIdx.x < 4096) {
        // =================== CONV PATH ===================
        float* xs = smem;                 // 11 rows x 32 (col idx = gc+1)
        float* h1 = smem + XS_FL;         // [lr 0..8][cp 0..29][c], stride 36
        float* Gs = h1 + H1_FL;           // [p 0..195][c], stride 36

        int b = blockIdx.x >> 2;
        int base = 7 * (blockIdx.x & 3);  // output row base: 0,7,14,21

        for (int i = tid; i < XS_FL; i += 288) {
            int r = i >> 5, c = i & 31;
            int gr = base - 2 + r, gc = c - 1;
            float v = 0.0f;
            if (gr >= 0 && gr < 28 && gc >= 0 && gc < 28)
                v = x[b * 784 + gr * 28 + gc];
            xs[i] = v;
        }
        for (int i = tid; i < 9 * 2 * 32; i += 288) {
            int lr = i >> 6;
            int cp = ((i >> 5) & 1) ? 29 : 0;
            int c = i & 31;
            h1[(lr * 30 + cp) * 36 + c] = 0.0f;
        }
        __syncthreads();

        // ---- conv1: lane = channel, warp = h1 local row (9 warps, 9 rows)
        {
            int c = lane;
            float wk[9];
            #pragma unroll
            for (int k = 0; k < 9; k++) wk[k] = w1[k * 32 + c];
            float bc = b1[c];

            int lr = wid;                        // 0..8
            int gr = base - 1 + lr;
            float* hrow = h1 + (lr * 30 + 1) * 36 + c;
            if (gr < 0 || gr >= 28) {
                #pragma unroll 4
                for (int col = 0; col < 28; col++) hrow[col * 36] = 0.0f;
            } else {
                const float* xr = xs + lr * 32;  // x rows lr, lr+1, lr+2
                float a0 = xr[0],   b0 = xr[1];
                float a1v = xr[32], b1v = xr[33];
                float a2v = xr[64], b2v = xr[65];
                #pragma unroll 4
                for (int col = 0; col < 28; col++) {
                    float c0  = xr[col + 2];
                    float c1v = xr[32 + col + 2];
                    float c2v = xr[64 + col + 2];
                    float acc = bc;
                    acc += a0  * wk[0]; acc += b0  * wk[1]; acc += c0  * wk[2];
                    acc += a1v * wk[3]; acc += b1v * wk[4]; acc += c1v * wk[5];
                    acc += a2v * wk[6]; acc += b2v * wk[7]; acc += c2v * wk[8];
                    hrow[col * 36] = fmaxf(acc, 0.0f);
                    a0 = b0;   b0 = c0;
                    a1v = b1v; b1v = c1v;
                    a2v = b2v; b2v = c2v;
                }
            }
        }
        __syncthreads();

        // ---- G-pass: lane = channel, warp = output row r (warps 0..6)
        if (wid < 7) {
            int c = lane, r = wid;
            float wk[9];
            #pragma unroll
            for (int k = 0; k < 9; k++) wk[k] = w2[k * 32 + c];
            const float* h0 = h1 + ((r    ) * 30) * 36 + c;
            const float* hm = h1 + ((r + 1) * 30) * 36 + c;
            const float* h2 = h1 + ((r + 2) * 30) * 36 + c;
            float a0 = h0[0],  b0 = h0[36];
            float a1 = hm[0],  b1v = hm[36];
            float a2 = h2[0],  b2v = h2[36];
            float* grow = Gs + r * 28 * 36 + c;
            #pragma unroll 4
            for (int col = 0; col < 28; col++) {
                float c0 = h0[(col + 2) * 36];
                float c1 = hm[(col + 2) * 36];
                float c2 = h2[(col + 2) * 36];
                float acc;
                acc  = a0  * wk[0]; acc += b0  * wk[1]; acc += c0 * wk[2];
                acc += a1  * wk[3]; acc += b1v * wk[4]; acc += c1 * wk[5];
                acc += a2  * wk[6]; acc += b2v * wk[7]; acc += c2 * wk[8];
                grow[col * 36] = acc;
                a0 = b0;   b0 = c0;
                a1 = b1v;  b1v = c1;
                a2 = b2v;  b2v = c2;
            }
        }
        __syncthreads();

        // ---- sum-pass: thread = pixel p (0..195)
        if (tid < 196) {
            unsigned saddr = (unsigned)__cvta_generic_to_shared(Gs + tid * 36);
            unsigned long long s0, s1, s2, s3, s4, s5, s6, s7;
            {
                unsigned long long d0, d1, d2, d3;
                lds_v2u64(d0, d1, saddr);
                lds_v2u64(d2, d3, saddr + 16);
                s0 = d0; s1 = d1; s2 = d2; s3 = d3;
                lds_v2u64(d0, d1, saddr + 32);
                lds_v2u64(d2, d3, saddr + 48);
                s4 = d0; s5 = d1; s6 = d2; s7 = d3;
                lds_v2u64(d0, d1, saddr + 64);
                lds_v2u64(d2, d3, saddr + 80);
                s0 = addf2(s0, d0); s1 = addf2(s1, d1);
                s2 = addf2(s2, d2); s3 = addf2(s3, d3);
                lds_v2u64(d0, d1, saddr + 96);
                lds_v2u64(d2, d3, saddr + 112);
                s4 = addf2(s4, d0); s5 = addf2(s5, d1);
                s6 = addf2(s6, d2); s7 = addf2(s7, d3);
            }
            s0 = addf2(s0, s4); s1 = addf2(s1, s5);
            s2 = addf2(s2, s6); s3 = addf2(s3, s7);
            s0 = addf2(s0, s2); s1 = addf2(s1, s3);
            s0 = addf2(s0, s1);
            float lo, hi;
            upk2(lo, hi, s0);
            float acc = lo + hi + b2[0];
            z_buf[b * ZDIM + base * 28 + tid] = fmaxf(acc, 0.0f);
        }
        return;
    }

    // =================== TDA PATH ===================
    {
        int b = blockIdx.x - 4096;
        float* red  = smem;            // 9 warps x 6
        float* fin  = smem + 64;       // 6
        float* lam1 = smem + 80;       // 64
        float* lam2 = smem + 144;      // 64

        const float4* v1 = (const float4*)(dtm1 + b * PIX);
        const float4* v2 = (const float4*)(dtm2 + b * PIX);

        float mx1 = -1e30f, a1 = 1e30f, a2 = 1e30f;
        float mx2 = -1e30f, c1 = 1e30f, c2 = 1e30f;
        if (tid < 196) {
            float4 u4 = v1[tid];
            float4 w4 = v2[tid];
            #pragma unroll
            for (int j = 0; j < 4; j++) {
                float u = (j == 0) ? u4.x : (j == 1) ? u4.y : (j == 2) ? u4.z : u4.w;
                mx1 = fmaxf(mx1, u);
                if (u < a1) { a2 = a1; a1 = u; } else if (u < a2) a2 = u;
                float w = (j == 0) ? w4.x : (j == 1) ? w4.y : (j == 2) ? w4.z : w4.w;
                mx2 = fmaxf(mx2, w);
                if (w < c1) { c2 = c1; c1 = w; } else if (w < c2) c2 = w;
            }
        }
        #pragma unroll
        for (int off = 16; off; off >>= 1) {
            mx1 = fmaxf(mx1, __shfl_xor_sync(~0u, mx1, off));
            float o1 = __shfl_xor_sync(~0u, a1, off);
            float o2 = __shfl_xor_sync(~0u, a2, off);
            float n1 = fminf(a1, o1);
            float n2 = fminf(fmaxf(a1, o1), fminf(a2, o2));
            a1 = n1; a2 = n2;
            mx2 = fmaxf(mx2, __shfl_xor_sync(~0u, mx2, off));
            float p1 = __shfl_xor_sync(~0u, c1, off);
            float p2 = __shfl_xor_sync(~0u, c2, off);
            float q1 = fminf(c1, p1);
            float q2 = fminf(fmaxf(c1, p1), fminf(c2, p2));
            c1 = q1; c2 = q2;
        }
        if (lane == 0) {
            red[wid * 6 + 0] = mx1; red[wid * 6 + 1] = a1; red[wid * 6 + 2] = a2;
            red[wid * 6 + 3] = mx2; red[wid * 6 + 4] = c1; red[wid * 6 + 5] = c2;
        }
        __syncthreads();
        if (tid == 0) {
            float M1 = red[0], A1 = red[1], A2 = red[2];
            float M2 = red[3], C1 = red[4], C2 = red[5];
            #pragma unroll
            for (int w = 1; w < 9; w++) {
                M1 = fmaxf(M1, red[w * 6 + 0]);
                float o1 = red[w * 6 + 1], o2 = red[w * 6 + 2];
                float n1 = fminf(A1, o1);
                float n2 = fminf(fmaxf(A1, o1), fminf(A2, o2));
                A1 = n1; A2 = n2;
                M2 = fmaxf(M2, red[w * 6 + 3]);
                float p1 = red[w * 6 + 4], p2 = red[w * 6 + 5];
                float q1 = fminf(C1, p1);
                float q2 = fminf(fmaxf(C1, p1), fminf(C2, p2));
                C1 = q1; C2 = q2;
            }
            fin[0] = M1; fin[1] = A1; fin[2] = A2;
            fin[3] = M2; fin[4] = C1; fin[5] = C2;
        }
        __syncthreads();

        if (tid < 128) {
            int k = (tid >> 5) & 1, t = tid & 31;
            if (tid < 64) {
                float tv1 = 0.01f + (float)t * (0.28f / 31.0f);
                float m1 = k ? fin[2] : fin[1];
                lam1[tid] = fmaxf(0.0f, fminf(tv1 - m1, fin[0] - tv1));
            } else {
                float tv2 = 0.05f + (float)t * (0.25f / 31.0f);
                float m2 = k ? fin[5] : fin[4];
                lam2[tid - 64] = fmaxf(0.0f, fminf(tv2 - m2, fin[3] - tv2));
            }
        }
        __syncthreads();

        if (tid < 32) {
            float acc = g1b[tid];
            #pragma unroll
            for (int i = 0; i < 64; i++) acc += lam1[i] * g1w[i * 32 + tid];
            z_buf[b * ZDIM + 784 + tid] = fmaxf(acc, 0.0f);
        } else if (tid < 64) {
            int j = tid - 32;
            float acc = g2b[j];
            #pragma unroll
            for (int i = 0; i < 64; i++) acc += lam2[i] * g2w[i * 32 + j];
            z_buf[b * ZDIM + 816 + j] = fmaxf(acc, 0.0f);
        }
    }
}

// ---------------------------------------------------------------------------
// MLP head v3: GEMM-style, weight-register-stationary across 8 samples.
//   Grid 128, 256 threads = 16 row-segments (seg) x 16 col-groups (cg).
//   Thread: rows [seg*53, seg*53+53), cols [4cg, 4cg+4), 8 samples.
//     - fc1w via LDG.128 (53 loads, each reused for 8 samples)
//     - z via transposed smem zt[row][s] (stride 12 floats, 16B aligned)
//     - 32 accumulators; segment reduction via 17-padded smem; fused fc2.
//   smem floats: zt 848*12=10176 | part 512*17=8704 | ys 8*68=544 => 76.7 KB
// ---------------------------------------------------------------------------
#define ZT_FL   (ZDIM * 12)
#define PART_FL (512 * 17)
#define YS_FL   (8 * 68)
#define MSMEM_FLOATS (ZT_FL + PART_FL + YS_FL)

__global__ void __launch_bounds__(256) mlp_kernel(
    const float* __restrict__ fc1w, const float* __restrict__ fc1b,
    const float* __restrict__ fc2w, const float* __restrict__ fc2b,
    float* __restrict__ out)
{
    extern __shared__ float msmem[];
    float* zt   = msmem;                 // [row][s], stride 12
    float* part = msmem + ZT_FL;         // [(s*64+c)*17 + seg]
    float* ys   = part + PART_FL;        // [s][68]

    int tid = threadIdx.x;
    int bbase = blockIdx.x * 8;

    // ---- load z for 8 samples, transposed: zt[row*12 + s]
    {
        const float4* zb4 = (const float4*)(z_buf + (size_t)bbase * ZDIM);
        for (int i = tid; i < 8 * (ZDIM / 4); i += 256) {
            int s = i / (ZDIM / 4);
            int r4 = i - s * (ZDIM / 4);
            float4 v = zb4[i];
            int r = r4 * 4;
            zt[(r + 0) * 12 + s] = v.x;
            zt[(r + 1) * 12 + s] = v.y;
            zt[(r + 2) * 12 + s] = v.z;
            zt[(r + 3) * 12 + s] = v.w;
        }
    }
    __syncthreads();

    // ---- fc1 partials: thread (seg, cg)
    {
        int seg = tid >> 4, cg = tid & 15;
        int r0 = seg * 53;
        const float4* wrow = (const float4*)fc1w + cg;   // + row*16

        float acc[8][4];
        #pragma unroll
        for (int s = 0; s < 8; s++)
            #pragma unroll
            for (int c = 0; c < 4; c++) acc[s][c] = 0.0f;

        #pragma unroll 4
        for (int r = r0; r < r0 + 53; r++) {
            float4 w = wrow[r * 16];
            float4 zA = *(const float4*)(zt + r * 12);       // samples 0..3
            float4 zB = *(const float4*)(zt + r * 12 + 4);   // samples 4..7
            acc[0][0] += zA.x * w.x; acc[0][1] += zA.x * w.y;
            acc[0][2] += zA.x * w.z; acc[0][3] += zA.x * w.w;
            acc[1][0] += zA.y * w.x; acc[1][1] += zA.y * w.y;
            acc[1][2] += zA.y * w.z; acc[1][3] += zA.y * w.w;
            acc[2][0] += zA.z * w.x; acc[2][1] += zA.z * w.y;
            acc[2][2] += zA.z * w.z; acc[2][3] += zA.z * w.w;
            acc[3][0] += zA.w * w.x; acc[3][1] += zA.w * w.y;
            acc[3][2] += zA.w * w.z; acc[3][3] += zA.w * w.w;
            acc[4][0] += zB.x * w.x; acc[4][1] += zB.x * w.y;
            acc[4][2] += zB.x * w.z; acc[4][3] += zB.x * w.w;
            acc[5][0] += zB.y * w.x; acc[5][1] += zB.y * w.y;
            acc[5][2] += zB.y * w.z; acc[5][3] += zB.y * w.w;
            acc[6][0] += zB.z * w.x; acc[6][1] += zB.z * w.y;
            acc[6][2] += zB.z * w.z; acc[6][3] += zB.z * w.w;
            acc[7][0] += zB.w * w.x; acc[7][1] += zB.w * w.y;
            acc[7][2] += zB.w * w.z; acc[7][3] += zB.w * w.w;
        }

        #pragma unroll
        for (int s = 0; s < 8; s++)
            #pragma unroll
            for (int c = 0; c < 4; c++)
                part[(s * 64 + cg * 4 + c) * 17 + seg] = acc[s][c];
    }
    __syncthreads();

    // ---- reduce 16 segments -> ys (relu + bias)
    for (int o = tid; o < 512; o += 256) {
        const float* pp = part + o * 17;
        float s0 = 0.0f, s1 = 0.0f, s2 = 0.0f, s3 = 0.0f;
        #pragma unroll
        for (int g = 0; g < 4; g++) {
            s0 += pp[4 * g + 0];
            s1 += pp[4 * g + 1];
            s2 += pp[4 * g + 2];
            s3 += pp[4 * g + 3];
        }
        int s = o >> 6, c = o & 63;
        ys[s * 68 + c] = fmaxf((s0 + s1) + (s2 + s3) + fc1b[c], 0.0f);
    }
    __syncthreads();

    // ---- fc2
    if (tid < 80) {
        int s = tid / 10, k = tid - s * 10;
        float acc = fc2b[k];
        #pragma unroll
        for (int jj = 0; jj < 64; jj++)
            acc += ys[s * 68 + jj] * fc2w[jj * 10 + k];
        out[(bbase + s) * 10 + k] = acc;
    }
}

// ---------------------------------------------------------------------------
extern "C" void kernel_launch(void* const* d_in, const int* in_sizes, int n_in,
                              void* d_out, int out_size)
{
    const float* x    = (const float*)d_in[0];
    const float* dtm1 = (const float*)d_in[1];
    const float* dtm2 = (const float*)d_in[2];
    const float* w1   = (const float*)d_in[3];
    const float* b1   = (const float*)d_in[4];
    const float* w2   = (const float*)d_in[5];
    const float* b2   = (const float*)d_in[6];
    const float* g1w  = (const float*)d_in[7];
    const float* g1b  = (const float*)d_in[8];
    const float* g2w  = (const float*)d_in[9];
    const float* g2b  = (const float*)d_in[10];
    const float* fc1w = (const float*)d_in[11];
    const float* fc1b = (const float*)d_in[12];
    const float* fc2w = (const float*)d_in[13];
    const float* fc2b = (const float*)d_in[14];
    float* out = (float*)d_out;

    cudaFuncSetAttribute(fused_kernel, cudaFuncAttributeMaxDynamicSharedMemorySize,
                         CSMEM_FLOATS * (int)sizeof(float));
    cudaFuncSetAttribute(fused_kernel, cudaFuncAttributePreferredSharedMemoryCarveout,
                         100);
    cudaFuncSetAttribute(mlp_kernel, cudaFuncAttributeMaxDynamicSharedMemorySize,
                         MSMEM_FLOATS * (int)sizeof(float));

    fused_kernel<<<4096 + NB, 288, CSMEM_FLOATS * sizeof(float)>>>(
        x, w1, b1, w2, b2, dtm1, dtm2, g1w, g1b, g2w, g2b);
    mlp_kernel<<<NB / 8, 256, MSMEM_FLOATS * sizeof(float)>>>(
        fc1w, fc1b, fc2w, fc2b, out);
}

// round 11
// speedup vs baseline: 1.8850x; 1.0393x over previous
#include <cuda_runtime.h>

#define NB 1024
#define PIX 784
#define ZDIM 848

__device__ float z_buf[NB * ZDIM];

// ---------------- packed f32x2 helpers ----------------
__device__ __forceinline__ void lds_v2u64(unsigned long long &a, unsigned long long &b,
                                          unsigned saddr) {
    asm volatile("ld.shared.v2.u64 {%0,%1},[%2];" : "=l"(a), "=l"(b) : "r"(saddr));
}
__device__ __forceinline__ unsigned long long addf2(unsigned long long a,
                                                    unsigned long long b) {
    unsigned long long r;
    asm("add.rn.f32x2 %0,%1,%2;" : "=l"(r) : "l"(a), "l"(b));
    return r;
}
__device__ __forceinline__ void upk2(float &lo, float &hi, unsigned long long v) {
    asm("mov.b64 {%0,%1},%2;" : "=f"(lo), "=f"(hi) : "l"(v));
}

// ---------------------------------------------------------------------------
// Fused kernel. Blocks [0,4096): conv quarter-tiles. Blocks [4096,5120): TDA.
// (unchanged — protected win)
// ---------------------------------------------------------------------------
#define XS_FL   (11 * 32)
#define H1_FL   (9 * 30 * 36)
#define G_FL    (196 * 36)
#define CSMEM_FLOATS (XS_FL + H1_FL + G_FL)

__global__ void __launch_bounds__(288, 3) fused_kernel(
    const float* __restrict__ x,
    const float* __restrict__ w1, const float* __restrict__ b1,
    const float* __restrict__ w2, const float* __restrict__ b2,
    const float* __restrict__ dtm1, const float* __restrict__ dtm2,
    const float* __restrict__ g1w, const float* __restrict__ g1b,
    const float* __restrict__ g2w, const float* __restrict__ g2b)
{
    extern __shared__ float smem[];
    int tid = threadIdx.x;
    int lane = tid & 31, wid = tid >> 5;

    if (blockIdx.x < 4096) {
        // =================== CONV PATH ===================
        float* xs = smem;                 // 11 rows x 32 (col idx = gc+1)
        float* h1 = smem + XS_FL;         // [lr 0..8][cp 0..29][c], stride 36
        float* Gs = h1 + H1_FL;           // [p 0..195][c], stride 36

        int b = blockIdx.x >> 2;
        int base = 7 * (blockIdx.x & 3);  // output row base: 0,7,14,21

        for (int i = tid; i < XS_FL; i += 288) {
            int r = i >> 5, c = i & 31;
            int gr = base - 2 + r, gc = c - 1;
            float v = 0.0f;
            if (gr >= 0 && gr < 28 && gc >= 0 && gc < 28)
                v = x[b * 784 + gr * 28 + gc];
            xs[i] = v;
        }
        for (int i = tid; i < 9 * 2 * 32; i += 288) {
            int lr = i >> 6;
            int cp = ((i >> 5) & 1) ? 29 : 0;
            int c = i & 31;
            h1[(lr * 30 + cp) * 36 + c] = 0.0f;
        }
        __syncthreads();

        // ---- conv1: lane = channel, warp = h1 local row (9 warps, 9 rows)
        {
            int c = lane;
            float wk[9];
            #pragma unroll
            for (int k = 0; k < 9; k++) wk[k] = w1[k * 32 + c];
            float bc = b1[c];

            int lr = wid;                        // 0..8
            int gr = base - 1 + lr;
            float* hrow = h1 + (lr * 30 + 1) * 36 + c;
            if (gr < 0 || gr >= 28) {
                #pragma unroll 4
                for (int col = 0; col < 28; col++) hrow[col * 36] = 0.0f;
            } else {
                const float* xr = xs + lr * 32;  // x rows lr, lr+1, lr+2
                float a0 = xr[0],   b0 = xr[1];
                float a1v = xr[32], b1v = xr[33];
                float a2v = xr[64], b2v = xr[65];
                #pragma unroll 4
                for (int col = 0; col < 28; col++) {
                    float c0  = xr[col + 2];
                    float c1v = xr[32 + col + 2];
                    float c2v = xr[64 + col + 2];
                    float acc = bc;
                    acc += a0  * wk[0]; acc += b0  * wk[1]; acc += c0  * wk[2];
                    acc += a1v * wk[3]; acc += b1v * wk[4]; acc += c1v * wk[5];
                    acc += a2v * wk[6]; acc += b2v * wk[7]; acc += c2v * wk[8];
                    hrow[col * 36] = fmaxf(acc, 0.0f);
                    a0 = b0;   b0 = c0;
                    a1v = b1v; b1v = c1v;
                    a2v = b2v; b2v = c2v;
                }
            }
        }
        __syncthreads();

        // ---- G-pass: lane = channel, warp = output row r (warps 0..6)
        if (wid < 7) {
            int c = lane, r = wid;
            float wk[9];
            #pragma unroll
            for (int k = 0; k < 9; k++) wk[k] = w2[k * 32 + c];
            const float* h0 = h1 + ((r    ) * 30) * 36 + c;
            const float* hm = h1 + ((r + 1) * 30) * 36 + c;
            const float* h2 = h1 + ((r + 2) * 30) * 36 + c;
            float a0 = h0[0],  b0 = h0[36];
            float a1 = hm[0],  b1v = hm[36];
            float a2 = h2[0],  b2v = h2[36];
            float* grow = Gs + r * 28 * 36 + c;
            #pragma unroll 4
            for (int col = 0; col < 28; col++) {
                float c0 = h0[(col + 2) * 36];
                float c1 = hm[(col + 2) * 36];
                float c2 = h2[(col + 2) * 36];
                float acc;
                acc  = a0  * wk[0]; acc += b0  * wk[1]; acc += c0 * wk[2];
                acc += a1  * wk[3]; acc += b1v * wk[4]; acc += c1 * wk[5];
                acc += a2  * wk[6]; acc += b2v * wk[7]; acc += c2 * wk[8];
                grow[col * 36] = acc;
                a0 = b0;   b0 = c0;
                a1 = b1v;  b1v = c1;
                a2 = b2v;  b2v = c2;
            }
        }
        __syncthreads();

        // ---- sum-pass: thread = pixel p (0..195)
        if (tid < 196) {
            unsigned saddr = (unsigned)__cvta_generic_to_shared(Gs + tid * 36);
            unsigned long long s0, s1, s2, s3, s4, s5, s6, s7;
            {
                unsigned long long d0, d1, d2, d3;
                lds_v2u64(d0, d1, saddr);
                lds_v2u64(d2, d3, saddr + 16);
                s0 = d0; s1 = d1; s2 = d2; s3 = d3;
                lds_v2u64(d0, d1, saddr + 32);
                lds_v2u64(d2, d3, saddr + 48);
                s4 = d0; s5 = d1; s6 = d2; s7 = d3;
                lds_v2u64(d0, d1, saddr + 64);
                lds_v2u64(d2, d3, saddr + 80);
                s0 = addf2(s0, d0); s1 = addf2(s1, d1);
                s2 = addf2(s2, d2); s3 = addf2(s3, d3);
                lds_v2u64(d0, d1, saddr + 96);
                lds_v2u64(d2, d3, saddr + 112);
                s4 = addf2(s4, d0); s5 = addf2(s5, d1);
                s6 = addf2(s6, d2); s7 = addf2(s7, d3);
            }
            s0 = addf2(s0, s4); s1 = addf2(s1, s5);
            s2 = addf2(s2, s6); s3 = addf2(s3, s7);
            s0 = addf2(s0, s2); s1 = addf2(s1, s3);
            s0 = addf2(s0, s1);
            float lo, hi;
            upk2(lo, hi, s0);
            float acc = lo + hi + b2[0];
            z_buf[b * ZDIM + base * 28 + tid] = fmaxf(acc, 0.0f);
        }
        return;
    }

    // =================== TDA PATH ===================
    {
        int b = blockIdx.x - 4096;
        float* red  = smem;            // 9 warps x 6
        float* fin  = smem + 64;       // 6
        float* lam1 = smem + 80;       // 64
        float* lam2 = smem + 144;      // 64

        const float4* v1 = (const float4*)(dtm1 + b * PIX);
        const float4* v2 = (const float4*)(dtm2 + b * PIX);

        float mx1 = -1e30f, a1 = 1e30f, a2 = 1e30f;
        float mx2 = -1e30f, c1 = 1e30f, c2 = 1e30f;
        if (tid < 196) {
            float4 u4 = v1[tid];
            float4 w4 = v2[tid];
            #pragma unroll
            for (int j = 0; j < 4; j++) {
                float u = (j == 0) ? u4.x : (j == 1) ? u4.y : (j == 2) ? u4.z : u4.w;
                mx1 = fmaxf(mx1, u);
                if (u < a1) { a2 = a1; a1 = u; } else if (u < a2) a2 = u;
                float w = (j == 0) ? w4.x : (j == 1) ? w4.y : (j == 2) ? w4.z : w4.w;
                mx2 = fmaxf(mx2, w);
                if (w < c1) { c2 = c1; c1 = w; } else if (w < c2) c2 = w;
            }
        }
        #pragma unroll
        for (int off = 16; off; off >>= 1) {
            mx1 = fmaxf(mx1, __shfl_xor_sync(~0u, mx1, off));
            float o1 = __shfl_xor_sync(~0u, a1, off);
            float o2 = __shfl_xor_sync(~0u, a2, off);
            float n1 = fminf(a1, o1);
            float n2 = fminf(fmaxf(a1, o1), fminf(a2, o2));
            a1 = n1; a2 = n2;
            mx2 = fmaxf(mx2, __shfl_xor_sync(~0u, mx2, off));
            float p1 = __shfl_xor_sync(~0u, c1, off);
            float p2 = __shfl_xor_sync(~0u, c2, off);
            float q1 = fminf(c1, p1);
            float q2 = fminf(fmaxf(c1, p1), fminf(c2, p2));
            c1 = q1; c2 = q2;
        }
        if (lane == 0) {
            red[wid * 6 + 0] = mx1; red[wid * 6 + 1] = a1; red[wid * 6 + 2] = a2;
            red[wid * 6 + 3] = mx2; red[wid * 6 + 4] = c1; red[wid * 6 + 5] = c2;
        }
        __syncthreads();
        if (tid == 0) {
            float M1 = red[0], A1 = red[1], A2 = red[2];
            float M2 = red[3], C1 = red[4], C2 = red[5];
            #pragma unroll
            for (int w = 1; w < 9; w++) {
                M1 = fmaxf(M1, red[w * 6 + 0]);
                float o1 = red[w * 6 + 1], o2 = red[w * 6 + 2];
                float n1 = fminf(A1, o1);
                float n2 = fminf(fmaxf(A1, o1), fminf(A2, o2));
                A1 = n1; A2 = n2;
                M2 = fmaxf(M2, red[w * 6 + 3]);
                float p1 = red[w * 6 + 4], p2 = red[w * 6 + 5];
                float q1 = fminf(C1, p1);
                float q2 = fminf(fmaxf(C1, p1), fminf(C2, p2));
                C1 = q1; C2 = q2;
            }
            fin[0] = M1; fin[1] = A1; fin[2] = A2;
            fin[3] = M2; fin[4] = C1; fin[5] = C2;
        }
        __syncthreads();

        if (tid < 128) {
            int k = (tid >> 5) & 1, t = tid & 31;
            if (tid < 64) {
                float tv1 = 0.01f + (float)t * (0.28f / 31.0f);
                float m1 = k ? fin[2] : fin[1];
                lam1[tid] = fmaxf(0.0f, fminf(tv1 - m1, fin[0] - tv1));
            } else {
                float tv2 = 0.05f + (float)t * (0.25f / 31.0f);
                float m2 = k ? fin[5] : fin[4];
                lam2[tid - 64] = fmaxf(0.0f, fminf(tv2 - m2, fin[3] - tv2));
            }
        }
        __syncthreads();

        if (tid < 32) {
            float acc = g1b[tid];
            #pragma unroll
            for (int i = 0; i < 64; i++) acc += lam1[i] * g1w[i * 32 + tid];
            z_buf[b * ZDIM + 784 + tid] = fmaxf(acc, 0.0f);
        } else if (tid < 64) {
            int j = tid - 32;
            float acc = g2b[j];
            #pragma unroll
            for (int i = 0; i < 64; i++) acc += lam2[i] * g2w[i * 32 + j];
            z_buf[b * ZDIM + 816 + j] = fmaxf(acc, 0.0f);
        }
    }
}

// ---------------------------------------------------------------------------
// MLP head v4: GEMM-style, 4 samples/block, grid 256, depth-4 prefetch ring.
//   256 threads = 16 row-segments (seg) x 16 col-groups (cg).
//   Thread: rows [seg*53, seg*53+53), cols [4cg,4cg+4), 4 samples.
//   smem floats: zt 848*4=3392 | part 256*17=4352 | ys 4*68=272 => 32.1 KB
//   -> 2-3 CTAs/SM, 16-24 warps/SM (latency coverage for L2 weight loads).
// ---------------------------------------------------------------------------
#define ZT_FL   (ZDIM * 4)
#define PART_FL (256 * 17)
#define YS_FL   (4 * 68)
#define MSMEM_FLOATS (ZT_FL + PART_FL + YS_FL)

__global__ void __launch_bounds__(256) mlp_kernel(
    const float* __restrict__ fc1w, const float* __restrict__ fc1b,
    const float* __restrict__ fc2w, const float* __restrict__ fc2b,
    float* __restrict__ out)
{
    extern __shared__ float msmem[];
    float* zt   = msmem;                 // [row][s], stride 4 (16B aligned)
    float* part = msmem + ZT_FL;         // [(s*64+c)*17 + seg]
    float* ys   = part + PART_FL;        // [s][68]

    int tid = threadIdx.x;
    int bbase = blockIdx.x * 4;

    // ---- load z for 4 samples, transposed: zt[row*4 + s]
    {
        const float4* zb4 = (const float4*)(z_buf + (size_t)bbase * ZDIM);
        for (int i = tid; i < 4 * (ZDIM / 4); i += 256) {
            int s = i / (ZDIM / 4);
            int r4 = i - s * (ZDIM / 4);
            float4 v = zb4[i];
            int r = r4 * 4;
            zt[(r + 0) * 4 + s] = v.x;
            zt[(r + 1) * 4 + s] = v.y;
            zt[(r + 2) * 4 + s] = v.z;
            zt[(r + 3) * 4 + s] = v.w;
        }
    }
    __syncthreads();

    // ---- fc1 partials: thread (seg, cg), depth-4 ring on weight rows
    {
        int seg = tid >> 4, cg = tid & 15;
        int r0 = seg * 53;
        const float4* wrow = (const float4*)fc1w + cg;   // + row*16

        float acc[4][4];
        #pragma unroll
        for (int s = 0; s < 4; s++)
            #pragma unroll
            for (int c = 0; c < 4; c++) acc[s][c] = 0.0f;

        // prefetch ring: rows r0..r0+3, plus the tail row r0+52 early
        float4 wb[4];
        #pragma unroll
        for (int g = 0; g < 4; g++) wb[g] = wrow[(r0 + g) * 16];
        float4 wlast = wrow[(r0 + 52) * 16];

        #pragma unroll 1
        for (int it = 0; it < 12; it++) {          // rows r0 .. r0+47
            int rb = r0 + it * 4;
            #pragma unroll
            for (int g = 0; g < 4; g++) {
                float4 w = wb[g];
                wb[g] = wrow[(rb + g + 4) * 16];   // prefetch rows +4..+51
                float4 zv = *(const float4*)(zt + (rb + g) * 4);
                acc[0][0] += zv.x * w.x; acc[0][1] += zv.x * w.y;
                acc[0][2] += zv.x * w.z; acc[0][3] += zv.x * w.w;
                acc[1][0] += zv.y * w.x; acc[1][1] += zv.y * w.y;
                acc[1][2] += zv.y * w.z; acc[1][3] += zv.y * w.w;
                acc[2][0] += zv.z * w.x; acc[2][1] += zv.z * w.y;
                acc[2][2] += zv.z * w.z; acc[2][3] += zv.z * w.w;
                acc[3][0] += zv.w * w.x; acc[3][1] += zv.w * w.y;
                acc[3][2] += zv.w * w.z; acc[3][3] += zv.w * w.w;
            }
        }
        // rows r0+48..r0+51 from ring, then r0+52 from wlast
        #pragma unroll
        for (int g = 0; g < 5; g++) {
            float4 w = (g < 4) ? wb[g] : wlast;
            float4 zv = *(const float4*)(zt + (r0 + 48 + g) * 4);
            acc[0][0] += zv.x * w.x; acc[0][1] += zv.x * w.y;
            acc[0][2] += zv.x * w.z; acc[0][3] += zv.x * w.w;
            acc[1][0] += zv.y * w.x; acc[1][1] += zv.y * w.y;
            acc[1][2] += zv.y * w.z; acc[1][3] += zv.y * w.w;
            acc[2][0] += zv.z * w.x; acc[2][1] += zv.z * w.y;
            acc[2][2] += zv.z * w.z; acc[2][3] += zv.z * w.w;
            acc[3][0] += zv.w * w.x; acc[3][1] += zv.w * w.y;
            acc[3][2] += zv.w * w.z; acc[3][3] += zv.w * w.w;
        }

        #pragma unroll
        for (int s = 0; s < 4; s++)
            #pragma unroll
            for (int c = 0; c < 4; c++)
                part[(s * 64 + cg * 4 + c) * 17 + seg] = acc[s][c];
    }
    __syncthreads();

    // ---- reduce 16 segments -> ys (relu + bias); 256 outputs, 1/thread
    {
        int o = tid;                    // s = o>>6, c = o&63
        const float* pp = part + o * 17;
        float s0 = 0.0f, s1 = 0.0f, s2 = 0.0f, s3 = 0.0f;
        #pragma unroll
        for (int g = 0; g < 4; g++) {
            s0 += pp[4 * g + 0];
            s1 += pp[4 * g + 1];
            s2 += pp[4 * g + 2];
            s3 += pp[4 * g + 3];
        }
        int s = o >> 6, c = o & 63;
        ys[s * 68 + c] = fmaxf((s0 + s1) + (s2 + s3) + fc1b[c], 0.0f);
    }
    __syncthreads();

    // ---- fc2
    if (tid < 40) {
        int s = tid / 10, k = tid - s * 10;
        float acc = fc2b[k];
        #pragma unroll
        for (int jj = 0; jj < 64; jj++)
            acc += ys[s * 68 + jj] * fc2w[jj * 10 + k];
        out[(bbase + s) * 10 + k] = acc;
    }
}

// ---------------------------------------------------------------------------
extern "C" void kernel_launch(void* const* d_in, const int* in_sizes, int n_in,
                              void* d_out, int out_size)
{
    const float* x    = (const float*)d_in[0];
    const float* dtm1 = (const float*)d_in[1];
    const float* dtm2 = (const float*)d_in[2];
    const float* w1   = (const float*)d_in[3];
    const float* b1   = (const float*)d_in[4];
    const float* w2   = (const float*)d_in[5];
    const float* b2   = (const float*)d_in[6];
    const float* g1w  = (const float*)d_in[7];
    const float* g1b  = (const float*)d_in[8];
    const float* g2w  = (const float*)d_in[9];
    const float* g2b  = (const float*)d_in[10];
    const float* fc1w = (const float*)d_in[11];
    const float* fc1b = (const float*)d_in[12];
    const float* fc2w = (const float*)d_in[13];
    const float* fc2b = (const float*)d_in[14];
    float* out = (float*)d_out;

    cudaFuncSetAttribute(fused_kernel, cudaFuncAttributeMaxDynamicSharedMemorySize,
                         CSMEM_FLOATS * (int)sizeof(float));
    cudaFuncSetAttribute(fused_kernel, cudaFuncAttributePreferredSharedMemoryCarveout,
                         100);
    cudaFuncSetAttribute(mlp_kernel, cudaFuncAttributeMaxDynamicSharedMemorySize,
                         MSMEM_FLOATS * (int)sizeof(float));

    fused_kernel<<<4096 + NB, 288, CSMEM_FLOATS * sizeof(float)>>>(
        x, w1, b1, w2, b2, dtm1, dtm2, g1w, g1b, g2w, g2b);
    mlp_kernel<<<NB / 4, 256, MSMEM_FLOATS * sizeof(float)>>>(
        fc1w, fc1b, fc2w, fc2b, out);
}

// round 13
// speedup vs baseline: 1.8997x; 1.0078x over previous
#include <cuda_runtime.h>

#define NB 1024
#define PIX 784
#define ZDIM 848

__device__ float z_buf[NB * ZDIM];

// ---------------- packed f32x2 helpers ----------------
__device__ __forceinline__ void lds_v2u64(unsigned long long &a, unsigned long long &b,
                                          unsigned saddr) {
    asm volatile("ld.shared.v2.u64 {%0,%1},[%2];" : "=l"(a), "=l"(b) : "r"(saddr));
}
__device__ __forceinline__ unsigned long long addf2(unsigned long long a,
                                                    unsigned long long b) {
    unsigned long long r;
    asm("add.rn.f32x2 %0,%1,%2;" : "=l"(r) : "l"(a), "l"(b));
    return r;
}
__device__ __forceinline__ void upk2(float &lo, float &hi, unsigned long long v) {
    asm("mov.b64 {%0,%1},%2;" : "=f"(lo), "=f"(hi) : "l"(v));
}

// ---------------------------------------------------------------------------
// Fused kernel. Blocks [0,4096): conv quarter-tiles. Blocks [4096,5120): TDA.
//   R12: conv1/G-pass column loops fully unrolled (sliding window becomes
//   register renaming, no MOVs) + 3 independent accumulators per pixel.
// ---------------------------------------------------------------------------
#define XS_FL   (11 * 32)
#define H1_FL   (9 * 30 * 36)
#define G_FL    (196 * 36)
#define CSMEM_FLOATS (XS_FL + H1_FL + G_FL)

__global__ void __launch_bounds__(288, 3) fused_kernel(
    const float* __restrict__ x,
    const float* __restrict__ w1, const float* __restrict__ b1,
    const float* __restrict__ w2, const float* __restrict__ b2,
    const float* __restrict__ dtm1, const float* __restrict__ dtm2,
    const float* __restrict__ g1w, const float* __restrict__ g1b,
    const float* __restrict__ g2w, const float* __restrict__ g2b)
{
    extern __shared__ float smem[];
    int tid = threadIdx.x;
    int lane = tid & 31, wid = tid >> 5;

    if (blockIdx.x < 4096) {
        // =================== CONV PATH ===================
        float* xs = smem;                 // 11 rows x 32 (col idx = gc+1)
        float* h1 = smem + XS_FL;         // [lr 0..8][cp 0..29][c], stride 36
        float* Gs = h1 + H1_FL;           // [p 0..195][c], stride 36

        int b = blockIdx.x >> 2;
        int base = 7 * (blockIdx.x & 3);  // output row base: 0,7,14,21

        for (int i = tid; i < XS_FL; i += 288) {
            int r = i >> 5, c = i & 31;
            int gr = base - 2 + r, gc = c - 1;
            float v = 0.0f;
            if (gr >= 0 && gr < 28 && gc >= 0 && gc < 28)
                v = x[b * 784 + gr * 28 + gc];
            xs[i] = v;
        }
        for (int i = tid; i < 9 * 2 * 32; i += 288) {
            int lr = i >> 6;
            int cp = ((i >> 5) & 1) ? 29 : 0;
            int c = i & 31;
            h1[(lr * 30 + cp) * 36 + c] = 0.0f;
        }
        __syncthreads();

        // ---- conv1: lane = channel, warp = h1 local row (9 warps, 9 rows)
        {
            int c = lane;
            float wk[9];
            #pragma unroll
            for (int k = 0; k < 9; k++) wk[k] = w1[k * 32 + c];
            float bc = b1[c];

            int lr = wid;                        // 0..8
            int gr = base - 1 + lr;
            float* hrow = h1 + (lr * 30 + 1) * 36 + c;
            if (gr < 0 || gr >= 28) {
                #pragma unroll
                for (int col = 0; col < 28; col++) hrow[col * 36] = 0.0f;
            } else {
                const float* xr = xs + lr * 32;  // x rows lr, lr+1, lr+2
                float a0 = xr[0],   b0 = xr[1];
                float a1v = xr[32], b1v = xr[33];
                float a2v = xr[64], b2v = xr[65];
                #pragma unroll
                for (int col = 0; col < 28; col++) {
                    float c0  = xr[col + 2];
                    float c1v = xr[32 + col + 2];
                    float c2v = xr[64 + col + 2];
                    // 3 independent chains (one per kernel row)
                    float t0 = bc;
                    t0 += a0  * wk[0]; t0 += b0  * wk[1]; t0 += c0  * wk[2];
                    float t1 = a1v * wk[3];
                    t1 += b1v * wk[4]; t1 += c1v * wk[5];
                    float t2 = a2v * wk[6];
                    t2 += b2v * wk[7]; t2 += c2v * wk[8];
                    hrow[col * 36] = fmaxf((t0 + t1) + t2, 0.0f);
                    a0 = b0;   b0 = c0;
                    a1v = b1v; b1v = c1v;
                    a2v = b2v; b2v = c2v;
                }
            }
        }
        __syncthreads();

        // ---- G-pass: lane = channel, warp = output row r (warps 0..6)
        if (wid < 7) {
            int c = lane, r = wid;
            float wk[9];
            #pragma unroll
            for (int k = 0; k < 9; k++) wk[k] = w2[k * 32 + c];
            const float* h0 = h1 + ((r    ) * 30) * 36 + c;
            const float* hm = h1 + ((r + 1) * 30) * 36 + c;
            const float* h2 = h1 + ((r + 2) * 30) * 36 + c;
            float a0 = h0[0],  b0 = h0[36];
            float a1 = hm[0],  b1v = hm[36];
            float a2 = h2[0],  b2v = h2[36];
            float* grow = Gs + r * 28 * 36 + c;
            #pragma unroll
            for (int col = 0; col < 28; col++) {
                float c0 = h0[(col + 2) * 36];
                float c1 = hm[(col + 2) * 36];
                float c2 = h2[(col + 2) * 36];
                float t0 = a0  * wk[0];
                t0 += b0  * wk[1]; t0 += c0 * wk[2];
                float t1 = a1  * wk[3];
                t1 += b1v * wk[4]; t1 += c1 * wk[5];
                float t2 = a2  * wk[6];
                t2 += b2v * wk[7]; t2 += c2 * wk[8];
                grow[col * 36] = (t0 + t1) + t2;
                a0 = b0;   b0 = c0;
                a1 = b1v;  b1v = c1;
                a2 = b2v;  b2v = c2;
            }
        }
        __syncthreads();

        // ---- sum-pass: thread = pixel p (0..195)
        if (tid < 196) {
            unsigned saddr = (unsigned)__cvta_generic_to_shared(Gs + tid * 36);
            unsigned long long s0, s1, s2, s3, s4, s5, s6, s7;
            {
                unsigned long long d0, d1, d2, d3;
                lds_v2u64(d0, d1, saddr);
                lds_v2u64(d2, d3, saddr + 16);
                s0 = d0; s1 = d1; s2 = d2; s3 = d3;
                lds_v2u64(d0, d1, saddr + 32);
                lds_v2u64(d2, d3, saddr + 48);
                s4 = d0; s5 = d1; s6 = d2; s7 = d3;
                lds_v2u64(d0, d1, saddr + 64);
                lds_v2u64(d2, d3, saddr + 80);
                s0 = addf2(s0, d0); s1 = addf2(s1, d1);
                s2 = addf2(s2, d2); s3 = addf2(s3, d3);
                lds_v2u64(d0, d1, saddr + 96);
                lds_v2u64(d2, d3, saddr + 112);
                s4 = addf2(s4, d0); s5 = addf2(s5, d1);
                s6 = addf2(s6, d2); s7 = addf2(s7, d3);
            }
            s0 = addf2(s0, s4); s1 = addf2(s1, s5);
            s2 = addf2(s2, s6); s3 = addf2(s3, s7);
            s0 = addf2(s0, s2); s1 = addf2(s1, s3);
            s0 = addf2(s0, s1);
            float lo, hi;
            upk2(lo, hi, s0);
            float acc = lo + hi + b2[0];
            z_buf[b * ZDIM + base * 28 + tid] = fmaxf(acc, 0.0f);
        }
        return;
    }

    // =================== TDA PATH ===================
    {
        int b = blockIdx.x - 4096;
        float* red  = smem;            // 9 warps x 6
        float* fin  = smem + 64;       // 6
        float* lam1 = smem + 80;       // 64
        float* lam2 = smem + 144;      // 64

        const float4* v1 = (const float4*)(dtm1 + b * PIX);
        const float4* v2 = (const float4*)(dtm2 + b * PIX);

        float mx1 = -1e30f, a1 = 1e30f, a2 = 1e30f;
        float mx2 = -1e30f, c1 = 1e30f, c2 = 1e30f;
        if (tid < 196) {
            float4 u4 = v1[tid];
            float4 w4 = v2[tid];
            #pragma unroll
            for (int j = 0; j < 4; j++) {
                float u = (j == 0) ? u4.x : (j == 1) ? u4.y : (j == 2) ? u4.z : u4.w;
                mx1 = fmaxf(mx1, u);
                if (u < a1) { a2 = a1; a1 = u; } else if (u < a2) a2 = u;
                float w = (j == 0) ? w4.x : (j == 1) ? w4.y : (j == 2) ? w4.z : w4.w;
                mx2 = fmaxf(mx2, w);
                if (w < c1) { c2 = c1; c1 = w; } else if (w < c2) c2 = w;
            }
        }
        #pragma unroll
        for (int off = 16; off; off >>= 1) {
            mx1 = fmaxf(mx1, __shfl_xor_sync(~0u, mx1, off));
            float o1 = __shfl_xor_sync(~0u, a1, off);
            float o2 = __shfl_xor_sync(~0u, a2, off);
            float n1 = fminf(a1, o1);
            float n2 = fminf(fmaxf(a1, o1), fminf(a2, o2));
            a1 = n1; a2 = n2;
            mx2 = fmaxf(mx2, __shfl_xor_sync(~0u, mx2, off));
            float p1 = __shfl_xor_sync(~0u, c1, off);
            float p2 = __shfl_xor_sync(~0u, c2, off);
            float q1 = fminf(c1, p1);
            float q2 = fminf(fmaxf(c1, p1), fminf(c2, p2));
            c1 = q1; c2 = q2;
        }
        if (lane == 0) {
            red[wid * 6 + 0] = mx1; red[wid * 6 + 1] = a1; red[wid * 6 + 2] = a2;
            red[wid * 6 + 3] = mx2; red[wid * 6 + 4] = c1; red[wid * 6 + 5] = c2;
        }
        __syncthreads();
        if (tid == 0) {
            float M1 = red[0], A1 = red[1], A2 = red[2];
            float M2 = red[3], C1 = red[4], C2 = red[5];
            #pragma unroll
            for (int w = 1; w < 9; w++) {
                M1 = fmaxf(M1, red[w * 6 + 0]);
                float o1 = red[w * 6 + 1], o2 = red[w * 6 + 2];
                float n1 = fminf(A1, o1);
                float n2 = fminf(fmaxf(A1, o1), fminf(A2, o2));
                A1 = n1; A2 = n2;
                M2 = fmaxf(M2, red[w * 6 + 3]);
                float p1 = red[w * 6 + 4], p2 = red[w * 6 + 5];
                float q1 = fminf(C1, p1);
                float q2 = fminf(fmaxf(C1, p1), fminf(C2, p2));
                C1 = q1; C2 = q2;
            }
            fin[0] = M1; fin[1] = A1; fin[2] = A2;
            fin[3] = M2; fin[4] = C1; fin[5] = C2;
        }
        __syncthreads();

        if (tid < 128) {
            int k = (tid >> 5) & 1, t = tid & 31;
            if (tid < 64) {
                float tv1 = 0.01f + (float)t * (0.28f / 31.0f);
                float m1 = k ? fin[2] : fin[1];
                lam1[tid] = fmaxf(0.0f, fminf(tv1 - m1, fin[0] - tv1));
            } else {
                float tv2 = 0.05f + (float)t * (0.25f / 31.0f);
                float m2 = k ? fin[5] : fin[4];
                lam2[tid - 64] = fmaxf(0.0f, fminf(tv2 - m2, fin[3] - tv2));
            }
        }
        __syncthreads();

        if (tid < 32) {
            float acc = g1b[tid];
            #pragma unroll
            for (int i = 0; i < 64; i++) acc += lam1[i] * g1w[i * 32 + tid];
            z_buf[b * ZDIM + 784 + tid] = fmaxf(acc, 0.0f);
        } else if (tid < 64) {
            int j = tid - 32;
            float acc = g2b[j];
            #pragma unroll
            for (int i = 0; i < 64; i++) acc += lam2[i] * g2w[i * 32 + j];
            z_buf[b * ZDIM + 816 + j] = fmaxf(acc, 0.0f);
        }
    }
}

// ---------------------------------------------------------------------------
// MLP head v4 (unchanged): GEMM-style, 4 samples/block, grid 256, prefetch ring.
// ---------------------------------------------------------------------------
#define ZT_FL   (ZDIM * 4)
#define PART_FL (256 * 17)
#define YS_FL   (4 * 68)
#define MSMEM_FLOATS (ZT_FL + PART_FL + YS_FL)

__global__ void __launch_bounds__(256) mlp_kernel(
    const float* __restrict__ fc1w, const float* __restrict__ fc1b,
    const float* __restrict__ fc2w, const float* __restrict__ fc2b,
    float* __restrict__ out)
{
    extern __shared__ float msmem[];
    float* zt   = msmem;                 // [row][s], stride 4 (16B aligned)
    float* part = msmem + ZT_FL;         // [(s*64+c)*17 + seg]
    float* ys   = part + PART_FL;        // [s][68]

    int tid = threadIdx.x;
    int bbase = blockIdx.x * 4;

    {
        const float4* zb4 = (const float4*)(z_buf + (size_t)bbase * ZDIM);
        for (int i = tid; i < 4 * (ZDIM / 4); i += 256) {
            int s = i / (ZDIM / 4);
            int r4 = i - s * (ZDIM / 4);
            float4 v = zb4[i];
            int r = r4 * 4;
            zt[(r + 0) * 4 + s] = v.x;
            zt[(r + 1) * 4 + s] = v.y;
            zt[(r + 2) * 4 + s] = v.z;
            zt[(r + 3) * 4 + s] = v.w;
        }
    }
    __syncthreads();

    {
        int seg = tid >> 4, cg = tid & 15;
        int r0 = seg * 53;
        const float4* wrow = (const float4*)fc1w + cg;   // + row*16

        float acc[4][4];
        #pragma unroll
        for (int s = 0; s < 4; s++)
            #pragma unroll
            for (int c = 0; c < 4; c++) acc[s][c] = 0.0f;

        float4 wb[4];
        #pragma unroll
        for (int g = 0; g < 4; g++) wb[g] = wrow[(r0 + g) * 16];
        float4 wlast = wrow[(r0 + 52) * 16];

        #pragma unroll 1
        for (int it = 0; it < 12; it++) {          // rows r0 .. r0+47
            int rb = r0 + it * 4;
            #pragma unroll
            for (int g = 0; g < 4; g++) {
                float4 w = wb[g];
                wb[g] = wrow[(rb + g + 4) * 16];   // prefetch rows +4..+51
                float4 zv = *(const float4*)(zt + (rb + g) * 4);
                acc[0][0] += zv.x * w.x; acc[0][1] += zv.x * w.y;
                acc[0][2] += zv.x * w.z; acc[0][3] += zv.x * w.w;
                acc[1][0] += zv.y * w.x; acc[1][1] += zv.y * w.y;
                acc[1][2] += zv.y * w.z; acc[1][3] += zv.y * w.w;
                acc[2][0] += zv.z * w.x; acc[2][1] += zv.z * w.y;
                acc[2][2] += zv.z * w.z; acc[2][3] += zv.z * w.w;
                acc[3][0] += zv.w * w.x; acc[3][1] += zv.w * w.y;
                acc[3][2] += zv.w * w.z; acc[3][3] += zv.w * w.w;
            }
        }
        #pragma unroll
        for (int g = 0; g < 5; g++) {
            float4 w = (g < 4) ? wb[g] : wlast;
            float4 zv = *(const float4*)(zt + (r0 + 48 + g) * 4);
            acc[0][0] += zv.x * w.x; acc[0][1] += zv.x * w.y;
            acc[0][2] += zv.x * w.z; acc[0][3] += zv.x * w.w;
            acc[1][0] += zv.y * w.x; acc[1][1] += zv.y * w.y;
            acc[1][2] += zv.y * w.z; acc[1][3] += zv.y * w.w;
            acc[2][0] += zv.z * w.x; acc[2][1] += zv.z * w.y;
            acc[2][2] += zv.z * w.z; acc[2][3] += zv.z * w.w;
            acc[3][0] += zv.w * w.x; acc[3][1] += zv.w * w.y;
            acc[3][2] += zv.w * w.z; acc[3][3] += zv.w * w.w;
        }

        #pragma unroll
        for (int s = 0; s < 4; s++)
            #pragma unroll
            for (int c = 0; c < 4; c++)
                part[(s * 64 + cg * 4 + c) * 17 + seg] = acc[s][c];
    }
    __syncthreads();

    {
        int o = tid;                    // s = o>>6, c = o&63
        const float* pp = part + o * 17;
        float s0 = 0.0f, s1 = 0.0f, s2 = 0.0f, s3 = 0.0f;
        #pragma unroll
        for (int g = 0; g < 4; g++) {
            s0 += pp[4 * g + 0];
            s1 += pp[4 * g + 1];
            s2 += pp[4 * g + 2];
            s3 += pp[4 * g + 3];
        }
        int s = o >> 6, c = o & 63;
        ys[s * 68 + c] = fmaxf((s0 + s1) + (s2 + s3) + fc1b[c], 0.0f);
    }
    __syncthreads();

    if (tid < 40) {
        int s = tid / 10, k = tid - s * 10;
        float acc = fc2b[k];
        #pragma unroll
        for (int jj = 0; jj < 64; jj++)
            acc += ys[s * 68 + jj] * fc2w[jj * 10 + k];
        out[(bbase + s) * 10 + k] = acc;
    }
}

// ---------------------------------------------------------------------------
extern "C" void kernel_launch(void* const* d_in, const int* in_sizes, int n_in,
                              void* d_out, int out_size)
{
    const float* x    = (const float*)d_in[0];
    const float* dtm1 = (const float*)d_in[1];
    const float* dtm2 = (const float*)d_in[2];
    const float* w1   = (const float*)d_in[3];
    const float* b1   = (const float*)d_in[4];
    const float* w2   = (const float*)d_in[5];
    const float* b2   = (const float*)d_in[6];
    const float* g1w  = (const float*)d_in[7];
    const float* g1b  = (const float*)d_in[8];
    const float* g2w  = (const float*)d_in[9];
    const float* g2b  = (const float*)d_in[10];
    const float* fc1w = (const float*)d_in[11];
    const float* fc1b = (const float*)d_in[12];
    const float* fc2w = (const float*)d_in[13];
    const float* fc2b = (const float*)d_in[14];
    float* out = (float*)d_out;

    cudaFuncSetAttribute(fused_kernel, cudaFuncAttributeMaxDynamicSharedMemorySize,
                         CSMEM_FLOATS * (int)sizeof(float));
    cudaFuncSetAttribute(fused_kernel, cudaFuncAttributePreferredSharedMemoryCarveout,
                         100);
    cudaFuncSetAttribute(mlp_kernel, cudaFuncAttributeMaxDynamicSharedMemorySize,
                         MSMEM_FLOATS * (int)sizeof(float));

    fused_kernel<<<4096 + NB, 288, CSMEM_FLOATS * sizeof(float)>>>(
        x, w1, b1, w2, b2, dtm1, dtm2, g1w, g1b, g2w, g2b);
    mlp_kernel<<<NB / 4, 256, MSMEM_FLOATS * sizeof(float)>>>(
        fc1w, fc1b, fc2w, fc2b, out);
}